// round 1
// baseline (speedup 1.0000x reference)
#include <cuda_runtime.h>
#include <cuda_bf16.h>
#include <math_constants.h>

// Problem constants
#define BATCH 4
#define SEQ   4096
#define EMBED 512
#define HEAD  64

// ---------------- scratch (device globals; no allocation allowed) ----------
__device__ float gQ[BATCH * SEQ * HEAD];
__device__ float gK[BATCH * SEQ * HEAD];
__device__ float gV[BATCH * SEQ * HEAD];

// ============================================================================
// Kernel 1: fused KQV projection.  out[p] = x @ W[p]^T
// GEMM: M = B*T = 16384, N = 64 (per proj), K = 512.
// 64x64 output tile per block, 256 threads, 4x4 micro-tile per thread.
// Smem staged TRANSPOSED so the inner loop is 2x LDS.128 + 16 FFMA.
// ============================================================================
#define PPAD 68   // 64 + 4 pad, keeps float4 alignment (68*4 % 16 == 0)

__global__ __launch_bounds__(256) void proj_kernel(
    const float* __restrict__ x,
    const float* __restrict__ Wk,
    const float* __restrict__ Wq,
    const float* __restrict__ Wv)
{
    __shared__ float AsT[32][PPAD];   // [k][m]
    __shared__ float BsT[32][PPAD];   // [k][n]

    const int p = blockIdx.y;
    const float* __restrict__ W = (p == 0) ? Wk : (p == 1) ? Wq : Wv;
    float* __restrict__ out     = (p == 0) ? gK : (p == 1) ? gQ : gV;

    const int m0  = blockIdx.x * 64;
    const int tid = threadIdx.x;
    const int tx  = tid & 15;
    const int ty  = tid >> 4;

    float acc[4][4];
#pragma unroll
    for (int i = 0; i < 4; i++)
#pragma unroll
        for (int j = 0; j < 4; j++) acc[i][j] = 0.f;

    for (int k0 = 0; k0 < EMBED; k0 += 32) {
        // stage A chunk (x): 64 rows x 32 k, transposed into smem
#pragma unroll
        for (int it = 0; it < 8; it++) {
            int idx = tid + it * 256;        // 0..2047
            int row = idx >> 5;
            int k   = idx & 31;
            AsT[k][row] = x[(size_t)(m0 + row) * EMBED + k0 + k];
        }
        // stage B chunk (W): 64 rows x 32 k, transposed
#pragma unroll
        for (int it = 0; it < 8; it++) {
            int idx = tid + it * 256;
            int row = idx >> 5;
            int k   = idx & 31;
            BsT[k][row] = W[(size_t)row * EMBED + k0 + k];
        }
        __syncthreads();

#pragma unroll
        for (int kk = 0; kk < 32; kk++) {
            float4 a = *(const float4*)&AsT[kk][ty * 4];
            float4 b = *(const float4*)&BsT[kk][tx * 4];
            acc[0][0] += a.x * b.x; acc[0][1] += a.x * b.y; acc[0][2] += a.x * b.z; acc[0][3] += a.x * b.w;
            acc[1][0] += a.y * b.x; acc[1][1] += a.y * b.y; acc[1][2] += a.y * b.z; acc[1][3] += a.y * b.w;
            acc[2][0] += a.z * b.x; acc[2][1] += a.z * b.y; acc[2][2] += a.z * b.z; acc[2][3] += a.z * b.w;
            acc[3][0] += a.w * b.x; acc[3][1] += a.w * b.y; acc[3][2] += a.w * b.z; acc[3][3] += a.w * b.w;
        }
        __syncthreads();
    }

#pragma unroll
    for (int i = 0; i < 4; i++) {
        float4 v = make_float4(acc[i][0], acc[i][1], acc[i][2], acc[i][3]);
        *(float4*)&out[(size_t)(m0 + ty * 4 + i) * HEAD + tx * 4] = v;
    }
}

// ============================================================================
// Kernel 2: causal flash attention, fp32.
// One block per (batch, 64-query tile). 256 threads = 16x16, each thread owns
// a 4x4 micro-tile of S (scores) and of O (output).
// Smem: Qs[64][68] (natural), KsT[64][68] (transposed: [d][s]),
//       Vs[64][68] (natural: [s][d]), Ps[64][68].
// All inner-loop vector LDS are at a warp-uniform row -> conflict-free.
// ============================================================================
#define APAD 68
#define ATTN_SMEM (4 * 64 * APAD * sizeof(float))   // 69632 bytes

__global__ __launch_bounds__(256, 3) void attn_kernel(float* __restrict__ out)
{
    extern __shared__ float sm[];
    float* Qs  = sm;                  // [r][d]
    float* KsT = sm + 64 * APAD;      // [d][s]
    float* Vs  = sm + 2 * 64 * APAD;  // [s][d]
    float* Ps  = sm + 3 * 64 * APAD;  // [r][s]

    const int b   = blockIdx.y;
    const int qt  = (gridDim.x - 1) - blockIdx.x;   // big tiles launch first
    const int tid = threadIdx.x;
    const int tx  = tid & 15;
    const int ty  = tid >> 4;

    const float scale = rsqrtf((float)EMBED);

    const float* __restrict__ Qg = gQ + ((size_t)b * SEQ + qt * 64) * HEAD;

    // load Q tile (pre-scaled)
#pragma unroll
    for (int it = 0; it < 16; it++) {
        int idx = tid + it * 256;        // 0..4095
        int r = idx >> 6, d = idx & 63;
        Qs[r * APAD + d] = Qg[r * HEAD + d] * scale;
    }

    float O[4][4];
    float mrow[4], lrow[4];
#pragma unroll
    for (int i = 0; i < 4; i++) {
        mrow[i] = -CUDART_INF_F;
        lrow[i] = 0.f;
#pragma unroll
        for (int j = 0; j < 4; j++) O[i][j] = 0.f;
    }

    for (int kt = 0; kt <= qt; kt++) {
        const float* __restrict__ Kg = gK + ((size_t)b * SEQ + kt * 64) * HEAD;
        const float* __restrict__ Vg = gV + ((size_t)b * SEQ + kt * 64) * HEAD;

        __syncthreads();   // previous iteration done with Ps/KsT/Vs (also covers Qs on iter 0)
#pragma unroll
        for (int it = 0; it < 16; it++) {
            int idx = tid + it * 256;
            int r = idx >> 6, d = idx & 63;
            KsT[d * APAD + r] = Kg[r * HEAD + d];
            Vs[r * APAD + d]  = Vg[r * HEAD + d];
        }
        __syncthreads();

        // ---- S = Q @ K^T (4x4 micro-tile) ----
        float S[4][4];
#pragma unroll
        for (int i = 0; i < 4; i++)
#pragma unroll
            for (int j = 0; j < 4; j++) S[i][j] = 0.f;

#pragma unroll 4
        for (int d = 0; d < 64; d++) {
            float4 bk = *(const float4*)&KsT[d * APAD + tx * 4];
            float a0 = Qs[(ty * 4 + 0) * APAD + d];
            float a1 = Qs[(ty * 4 + 1) * APAD + d];
            float a2 = Qs[(ty * 4 + 2) * APAD + d];
            float a3 = Qs[(ty * 4 + 3) * APAD + d];
            S[0][0] += a0 * bk.x; S[0][1] += a0 * bk.y; S[0][2] += a0 * bk.z; S[0][3] += a0 * bk.w;
            S[1][0] += a1 * bk.x; S[1][1] += a1 * bk.y; S[1][2] += a1 * bk.z; S[1][3] += a1 * bk.w;
            S[2][0] += a2 * bk.x; S[2][1] += a2 * bk.y; S[2][2] += a2 * bk.z; S[2][3] += a2 * bk.w;
            S[3][0] += a3 * bk.x; S[3][1] += a3 * bk.y; S[3][2] += a3 * bk.z; S[3][3] += a3 * bk.w;
        }

        // causal mask on the diagonal tile
        if (kt == qt) {
#pragma unroll
            for (int i = 0; i < 4; i++) {
                int r = ty * 4 + i;
#pragma unroll
                for (int j = 0; j < 4; j++) {
                    int c = tx * 4 + j;
                    if (c > r) S[i][j] = -CUDART_INF_F;
                }
            }
        }

        // ---- online softmax ----
        float mt[4];
#pragma unroll
        for (int i = 0; i < 4; i++) {
            mt[i] = fmaxf(fmaxf(S[i][0], S[i][1]), fmaxf(S[i][2], S[i][3]));
        }
#pragma unroll
        for (int off = 1; off < 16; off <<= 1) {
#pragma unroll
            for (int i = 0; i < 4; i++)
                mt[i] = fmaxf(mt[i], __shfl_xor_sync(0xffffffffu, mt[i], off));
        }

        float corr[4], rsum[4];
#pragma unroll
        for (int i = 0; i < 4; i++) {
            float mnew = fmaxf(mrow[i], mt[i]);
            corr[i] = __expf(mrow[i] - mnew);
            mrow[i] = mnew;
            rsum[i] = 0.f;
        }

#pragma unroll
        for (int i = 0; i < 4; i++) {
            int r = ty * 4 + i;
#pragma unroll
            for (int j = 0; j < 4; j++) {
                float pv = __expf(S[i][j] - mrow[i]);
                Ps[r * APAD + tx * 4 + j] = pv;
                rsum[i] += pv;
            }
        }
#pragma unroll
        for (int off = 1; off < 16; off <<= 1) {
#pragma unroll
            for (int i = 0; i < 4; i++)
                rsum[i] += __shfl_xor_sync(0xffffffffu, rsum[i], off);
        }
#pragma unroll
        for (int i = 0; i < 4; i++) {
            lrow[i] = lrow[i] * corr[i] + rsum[i];
#pragma unroll
            for (int j = 0; j < 4; j++) O[i][j] *= corr[i];
        }

        __syncthreads();   // Ps fully written

        // ---- O += P @ V (4x4 micro-tile) ----
#pragma unroll 4
        for (int s = 0; s < 64; s++) {
            float4 v = *(const float4*)&Vs[s * APAD + tx * 4];
            float p0 = Ps[(ty * 4 + 0) * APAD + s];
            float p1 = Ps[(ty * 4 + 1) * APAD + s];
            float p2 = Ps[(ty * 4 + 2) * APAD + s];
            float p3 = Ps[(ty * 4 + 3) * APAD + s];
            O[0][0] += p0 * v.x; O[0][1] += p0 * v.y; O[0][2] += p0 * v.z; O[0][3] += p0 * v.w;
            O[1][0] += p1 * v.x; O[1][1] += p1 * v.y; O[1][2] += p1 * v.z; O[1][3] += p1 * v.w;
            O[2][0] += p2 * v.x; O[2][1] += p2 * v.y; O[2][2] += p2 * v.z; O[2][3] += p2 * v.w;
            O[3][0] += p3 * v.x; O[3][1] += p3 * v.y; O[3][2] += p3 * v.z; O[3][3] += p3 * v.w;
        }
    }

    // ---- finalize + write ----
    float* __restrict__ Og = out + ((size_t)b * SEQ + qt * 64) * HEAD;
#pragma unroll
    for (int i = 0; i < 4; i++) {
        float inv = 1.0f / lrow[i];
        float4 v = make_float4(O[i][0] * inv, O[i][1] * inv, O[i][2] * inv, O[i][3] * inv);
        *(float4*)&Og[(size_t)(ty * 4 + i) * HEAD + tx * 4] = v;
    }
}

// ============================================================================
// launch
// ============================================================================
extern "C" void kernel_launch(void* const* d_in, const int* in_sizes, int n_in,
                              void* d_out, int out_size)
{
    const float* x  = (const float*)d_in[0];
    const float* Wk = (const float*)d_in[1];
    const float* Wq = (const float*)d_in[2];
    const float* Wv = (const float*)d_in[3];
    float* out = (float*)d_out;

    // projections: 256 M-tiles x 3 projections
    proj_kernel<<<dim3(BATCH * SEQ / 64, 3), 256>>>(x, Wk, Wq, Wv);

    // attention: 64 query tiles x 4 batches
    cudaFuncSetAttribute(attn_kernel, cudaFuncAttributeMaxDynamicSharedMemorySize,
                         (int)ATTN_SMEM);
    attn_kernel<<<dim3(SEQ / 64, BATCH), 256, ATTN_SMEM>>>(out);
}

// round 3
// speedup vs baseline: 3.9300x; 3.9300x over previous
#include <cuda_runtime.h>
#include <cuda_fp16.h>
#include <cstdint>

#define BATCH 4
#define SEQ   4096
#define EMBED 512
#define HEAD  64
#define NTOK  (BATCH * SEQ)
#define QSCALE 0.04419417382415922f   // 512^-0.5

// ---------------- scratch (device globals) ----------------
__device__ __half gK16[NTOK * HEAD];   // [t][h]
__device__ __half gQ16[NTOK * HEAD];   // [t][h], pre-scaled
__device__ __half gVh [NTOK * HEAD];   // [t][h] hi part
__device__ __half gVl [NTOK * HEAD];   // [t][h] lo part
__device__ __half gW16[192 * EMBED];   // [Wk;Wq;Wv] rows, fp16

// ---------------- helpers ----------------
__device__ __forceinline__ uint32_t smem_u32(const void* p) {
    uint32_t a;
    asm("{ .reg .u64 t; cvta.to.shared.u64 t, %1; cvt.u32.u64 %0, t; }" : "=r"(a) : "l"(p));
    return a;
}
__device__ __forceinline__ void ldsm4(uint32_t* r, uint32_t addr) {
    asm volatile("ldmatrix.sync.aligned.m8n8.x4.shared.b16 {%0,%1,%2,%3}, [%4];"
                 : "=r"(r[0]), "=r"(r[1]), "=r"(r[2]), "=r"(r[3]) : "r"(addr));
}
__device__ __forceinline__ void ldsm4t(uint32_t* r, uint32_t addr) {
    asm volatile("ldmatrix.sync.aligned.m8n8.x4.trans.shared.b16 {%0,%1,%2,%3}, [%4];"
                 : "=r"(r[0]), "=r"(r[1]), "=r"(r[2]), "=r"(r[3]) : "r"(addr));
}
__device__ __forceinline__ void mma16816(float* c, const uint32_t* a, uint32_t b0, uint32_t b1) {
    asm volatile(
        "mma.sync.aligned.m16n8k16.row.col.f32.f16.f16.f32 "
        "{%0,%1,%2,%3}, {%4,%5,%6,%7}, {%8,%9}, {%0,%1,%2,%3};"
        : "+f"(c[0]), "+f"(c[1]), "+f"(c[2]), "+f"(c[3])
        : "r"(a[0]), "r"(a[1]), "r"(a[2]), "r"(a[3]), "r"(b0), "r"(b1));
}
__device__ __forceinline__ uint32_t packh(__half a, __half b) {
    __half2 t = __halves2half2(a, b);
    return *(uint32_t*)&t;
}

// ============================================================================
// Kernel 0: weights fp32 -> fp16, stacked [Wk;Wq;Wv] = [192][512]
// ============================================================================
__global__ void w16_kernel(const float* __restrict__ Wk, const float* __restrict__ Wq,
                           const float* __restrict__ Wv) {
    int i = blockIdx.x * 256 + threadIdx.x;
    if (i >= 192 * EMBED) return;
    int r = i >> 9, c = i & 511;
    float v = (r < 64) ? Wk[r * EMBED + c] : (r < 128) ? Wq[(r - 64) * EMBED + c]
                                                       : Wv[(r - 128) * EMBED + c];
    gW16[i] = __float2half_rn(v);
}

// ============================================================================
// Kernel 1: KQV projection via fp16 mma.sync, x split hi+lo.
// CTA: 64 rows x 192 cols, K-chunks of 64. 4 warps, warp = 16 m x 192 n.
// ============================================================================
#define PXH 0
#define PXL 8192
#define PWS 16384

__global__ __launch_bounds__(128) void proj_mma(const float* __restrict__ x)
{
    __shared__ __align__(16) uint8_t smem[40960];
    const uint32_t sb = smem_u32(smem);

    const int tid  = threadIdx.x;
    const int wid  = tid >> 5;
    const int lane = tid & 31;
    const int m0w  = wid * 16;
    const int g    = lane >> 2;
    const int tg   = lane & 3;
    const int mblk = blockIdx.x * 64;

    float c[24][4];
#pragma unroll
    for (int j = 0; j < 24; j++)
#pragma unroll
        for (int q = 0; q < 4; q++) c[j][q] = 0.f;

    for (int kc = 0; kc < 8; kc++) {
        __syncthreads();
        // stage x chunk (64 rows x 64 k) as hi/lo fp16, swizzled
#pragma unroll
        for (int it = 0; it < 8; it++) {
            int idx = tid + it * 128;          // 0..1023 float4s
            int r = idx >> 4, c4 = idx & 15;
            float4 f = *(const float4*)&x[(size_t)(mblk + r) * EMBED + kc * 64 + c4 * 4];
            __half hx = __float2half_rn(f.x), hy = __float2half_rn(f.y);
            __half hz = __float2half_rn(f.z), hw = __float2half_rn(f.w);
            __half lx = __float2half_rn(f.x - __half2float(hx));
            __half ly = __float2half_rn(f.y - __half2float(hy));
            __half lz = __float2half_rn(f.z - __half2float(hz));
            __half lw = __float2half_rn(f.w - __half2float(hw));
            uint32_t dst = r * 128 + ((c4 * 8) ^ ((r & 7) << 4));
            *(uint2*)(smem + PXH + dst) = make_uint2(packh(hx, hy), packh(hz, hw));
            *(uint2*)(smem + PXL + dst) = make_uint2(packh(lx, ly), packh(lz, lw));
        }
        // stage W chunk (192 rows x 64 k fp16), swizzled
#pragma unroll
        for (int it = 0; it < 12; it++) {
            int idx = tid + it * 128;          // 0..1535 uint4s
            int r = idx >> 3, u = idx & 7;
            uint32_t dst = r * 128 + ((u * 16) ^ ((r & 7) << 4));
            *(uint4*)(smem + PWS + dst) = *(const uint4*)&gW16[(size_t)r * EMBED + kc * 64 + u * 8];
        }
        __syncthreads();

#pragma unroll
        for (int ks = 0; ks < 4; ks++) {
            uint32_t ah[4], al[4];
            int arow = m0w + (lane & 15);
            uint32_t abyte = (uint32_t)((ks * 32 + (lane >> 4) * 16) ^ ((arow & 7) << 4));
            ldsm4(ah, sb + PXH + arow * 128 + abyte);
            ldsm4(al, sb + PXL + arow * 128 + abyte);
#pragma unroll
            for (int jj = 0; jj < 12; jj++) {
                uint32_t b[4];
                int brow = jj * 16 + (lane & 7) + ((lane >> 4) << 3);
                uint32_t bby = (uint32_t)((ks * 32 + ((lane >> 3) & 1) * 16) ^ ((brow & 7) << 4));
                ldsm4(b, sb + PWS + brow * 128 + bby);
                mma16816(c[2 * jj],     ah, b[0], b[1]);
                mma16816(c[2 * jj + 1], ah, b[2], b[3]);
                mma16816(c[2 * jj],     al, b[0], b[1]);
                mma16816(c[2 * jj + 1], al, b[2], b[3]);
            }
        }
    }

    // epilogue: cols 0-63 -> K, 64-127 -> Q (scaled), 128-191 -> V (hi/lo)
    const int m0 = mblk + m0w + g;
#pragma unroll
    for (int j = 0; j < 24; j++) {
        int col = j * 8 + 2 * tg;
        if (col < 64) {
            *(uint32_t*)&gK16[(size_t)m0 * HEAD + col] =
                packh(__float2half_rn(c[j][0]), __float2half_rn(c[j][1]));
            *(uint32_t*)&gK16[(size_t)(m0 + 8) * HEAD + col] =
                packh(__float2half_rn(c[j][2]), __float2half_rn(c[j][3]));
        } else if (col < 128) {
            int h = col - 64;
            *(uint32_t*)&gQ16[(size_t)m0 * HEAD + h] =
                packh(__float2half_rn(c[j][0] * QSCALE), __float2half_rn(c[j][1] * QSCALE));
            *(uint32_t*)&gQ16[(size_t)(m0 + 8) * HEAD + h] =
                packh(__float2half_rn(c[j][2] * QSCALE), __float2half_rn(c[j][3] * QSCALE));
        } else {
            int h = col - 128;
#pragma unroll
            for (int half_ = 0; half_ < 2; half_++) {
                int m = half_ ? (m0 + 8) : m0;
                float v0 = c[j][2 * half_], v1 = c[j][2 * half_ + 1];
                __half h0 = __float2half_rn(v0), h1 = __float2half_rn(v1);
                __half l0 = __float2half_rn(v0 - __half2float(h0));
                __half l1 = __float2half_rn(v1 - __half2float(h1));
                *(uint32_t*)&gVh[(size_t)m * HEAD + h] = packh(h0, h1);
                *(uint32_t*)&gVl[(size_t)m * HEAD + h] = packh(l0, l1);
            }
        }
    }
}

// ============================================================================
// Kernel 2: causal flash attention via fp16 mma.sync.
// CTA = 64 queries x 64-key tiles, 4 warps (warp = 16 q rows).
// No online max (scores bounded): l += sum(exp), O += P @ (Vh + Vl).
// ============================================================================
#define AQS 0
#define AKS 8192
#define AVH 16384
#define AVL 24576
#define APS 32768

__global__ __launch_bounds__(128) void attn_mma(float* __restrict__ out)
{
    __shared__ __align__(16) uint8_t smem[40960];
    const uint32_t sb = smem_u32(smem);

    // load-balance mapping: co-resident pairs (bid, bid+148) get big+small q-tiles
    const int bid = blockIdx.x;
    int rank;
    if (bid < 108)      rank = 40 + bid;
    else if (bid < 148) rank = bid - 108;
    else                rank = 255 - (bid - 148);
    const int qt = 63 - (rank >> 2);
    const int b  = rank & 3;

    const int tid  = threadIdx.x;
    const int wid  = tid >> 5;
    const int lane = tid & 31;
    const int m0w  = wid * 16;
    const int g    = lane >> 2;
    const int tg   = lane & 3;

    // stage Q tile (pre-scaled fp16), swizzled
    const __half* __restrict__ Qg = gQ16 + (size_t)(b * SEQ + qt * 64) * HEAD;
#pragma unroll
    for (int it = 0; it < 4; it++) {
        int idx = tid + it * 128;
        int r = idx >> 3, u = idx & 7;
        uint32_t dst = r * 128 + ((u * 16) ^ ((r & 7) << 4));
        *(uint4*)(smem + AQS + dst) = *(const uint4*)&Qg[r * HEAD + u * 8];
    }
    __syncthreads();

    uint32_t qa[4][4];
    {
        int arow = m0w + (lane & 15);
#pragma unroll
        for (int k4 = 0; k4 < 4; k4++) {
            uint32_t abyte = (uint32_t)((k4 * 32 + (lane >> 4) * 16) ^ ((arow & 7) << 4));
            ldsm4(qa[k4], sb + AQS + arow * 128 + abyte);
        }
    }

    float oc[8][4];
#pragma unroll
    for (int j = 0; j < 8; j++)
#pragma unroll
        for (int q = 0; q < 4; q++) oc[j][q] = 0.f;
    float ls0 = 0.f, ls1 = 0.f;

    for (int kt = 0; kt <= qt; kt++) {
        __syncthreads();   // everyone done with previous tile's K/V
        const __half* __restrict__ Kg  = gK16 + (size_t)(b * SEQ + kt * 64) * HEAD;
        const __half* __restrict__ Vhg = gVh  + (size_t)(b * SEQ + kt * 64) * HEAD;
        const __half* __restrict__ Vlg = gVl  + (size_t)(b * SEQ + kt * 64) * HEAD;
#pragma unroll
        for (int it = 0; it < 4; it++) {
            int idx = tid + it * 128;
            int r = idx >> 3, u = idx & 7;
            uint32_t dst = r * 128 + ((u * 16) ^ ((r & 7) << 4));
            int src = r * HEAD + u * 8;
            *(uint4*)(smem + AKS + dst) = *(const uint4*)&Kg[src];
            *(uint4*)(smem + AVH + dst) = *(const uint4*)&Vhg[src];
            *(uint4*)(smem + AVL + dst) = *(const uint4*)&Vlg[src];
        }
        __syncthreads();

        // ---- MMA1: S = Q @ K^T ----
        float sc[8][4];
#pragma unroll
        for (int j = 0; j < 8; j++)
#pragma unroll
            for (int q = 0; q < 4; q++) sc[j][q] = 0.f;
#pragma unroll
        for (int jj = 0; jj < 4; jj++) {
            int brow = jj * 16 + (lane & 7) + ((lane >> 4) << 3);
#pragma unroll
            for (int k4 = 0; k4 < 4; k4++) {
                uint32_t bby = (uint32_t)((k4 * 32 + ((lane >> 3) & 1) * 16) ^ ((brow & 7) << 4));
                uint32_t bk[4];
                ldsm4(bk, sb + AKS + brow * 128 + bby);
                mma16816(sc[2 * jj],     qa[k4], bk[0], bk[1]);
                mma16816(sc[2 * jj + 1], qa[k4], bk[2], bk[3]);
            }
        }

        // ---- mask + exp + P store ----
        const bool diag = (kt == qt);
        const int lr0 = m0w + g, lr1 = lr0 + 8;
#pragma unroll
        for (int jn = 0; jn < 8; jn++) {
            int c0 = jn * 8 + 2 * tg;
            float p0, p1, p2, p3;
            if (diag) {
                // local row vs local col (same 64-tile)
                p0 = (c0     <= lr0) ? __expf(sc[jn][0]) : 0.f;
                p1 = (c0 + 1 <= lr0) ? __expf(sc[jn][1]) : 0.f;
                p2 = (c0     <= lr1) ? __expf(sc[jn][2]) : 0.f;
                p3 = (c0 + 1 <= lr1) ? __expf(sc[jn][3]) : 0.f;
            } else {
                p0 = __expf(sc[jn][0]); p1 = __expf(sc[jn][1]);
                p2 = __expf(sc[jn][2]); p3 = __expf(sc[jn][3]);
            }
            ls0 += p0 + p1;
            ls1 += p2 + p3;
            *(uint32_t*)(smem + APS + lr0 * 128 + ((c0 * 2) ^ ((lr0 & 7) << 4))) =
                packh(__float2half_rn(p0), __float2half_rn(p1));
            *(uint32_t*)(smem + APS + lr1 * 128 + ((c0 * 2) ^ ((lr1 & 7) << 4))) =
                packh(__float2half_rn(p2), __float2half_rn(p3));
        }
        __syncwarp();

        // ---- MMA2: O += P @ Vh + P @ Vl ----
        uint32_t pa[4][4];
        {
            int arow = m0w + (lane & 15);
#pragma unroll
            for (int k4 = 0; k4 < 4; k4++) {
                uint32_t abyte = (uint32_t)((k4 * 32 + (lane >> 4) * 16) ^ ((arow & 7) << 4));
                ldsm4(pa[k4], sb + APS + arow * 128 + abyte);
            }
        }
#pragma unroll
        for (int jj = 0; jj < 4; jj++) {
#pragma unroll
            for (int k4 = 0; k4 < 4; k4++) {
                int krow = k4 * 16 + (lane & 7) + (((lane >> 3) & 1) << 3);
                uint32_t vby = (uint32_t)(((jj * 16 + ((lane >> 4) << 3)) * 2) ^ ((krow & 7) << 4));
                uint32_t bv[4];
                ldsm4t(bv, sb + AVH + krow * 128 + vby);
                mma16816(oc[2 * jj],     pa[k4], bv[0], bv[1]);
                mma16816(oc[2 * jj + 1], pa[k4], bv[2], bv[3]);
                ldsm4t(bv, sb + AVL + krow * 128 + vby);
                mma16816(oc[2 * jj],     pa[k4], bv[0], bv[1]);
                mma16816(oc[2 * jj + 1], pa[k4], bv[2], bv[3]);
            }
        }
    }

    // ---- epilogue ----
    ls0 += __shfl_xor_sync(0xffffffffu, ls0, 1);
    ls0 += __shfl_xor_sync(0xffffffffu, ls0, 2);
    ls1 += __shfl_xor_sync(0xffffffffu, ls1, 1);
    ls1 += __shfl_xor_sync(0xffffffffu, ls1, 2);
    const float inv0 = 1.0f / ls0;
    const float inv1 = 1.0f / ls1;

    const size_t ro = (size_t)(b * SEQ + qt * 64 + m0w + g) * HEAD;
#pragma unroll
    for (int jn = 0; jn < 8; jn++) {
        int col = jn * 8 + 2 * tg;
        float2 v0 = make_float2(oc[jn][0] * inv0, oc[jn][1] * inv0);
        float2 v1 = make_float2(oc[jn][2] * inv1, oc[jn][3] * inv1);
        *(float2*)&out[ro + col]            = v0;
        *(float2*)&out[ro + 8 * HEAD + col] = v1;
    }
}

// ============================================================================
// launch
// ============================================================================
extern "C" void kernel_launch(void* const* d_in, const int* in_sizes, int n_in,
                              void* d_out, int out_size)
{
    const float* x  = (const float*)d_in[0];
    const float* Wk = (const float*)d_in[1];
    const float* Wq = (const float*)d_in[2];
    const float* Wv = (const float*)d_in[3];
    float* out = (float*)d_out;

    w16_kernel<<<384, 256>>>(Wk, Wq, Wv);
    proj_mma<<<NTOK / 64, 128>>>(x);
    attn_mma<<<256, 128>>>(out);
}

// round 4
// speedup vs baseline: 6.8920x; 1.7537x over previous
#include <cuda_runtime.h>
#include <cuda_fp16.h>
#include <cstdint>

#define BATCH 4
#define SEQ   4096
#define EMBED 512
#define HEAD  64
#define NTOK  (BATCH * SEQ)
// C^-0.5 * log2(e): Q pre-scale so softmax uses raw ex2
#define QSC2  (0.04419417382415922f * 1.4426950408889634f)

// ---------------- scratch (device globals) ----------------
__device__ __half gK16[NTOK * HEAD];   // [t][h]
__device__ __half gQ16[NTOK * HEAD];   // [t][h], pre-scaled by QSC2
__device__ __half gV16[NTOK * HEAD];   // [t][h]
__device__ __half gW16[192 * EMBED];   // [Wk;Wq;Wv] rows, fp16

// ---------------- helpers ----------------
__device__ __forceinline__ uint32_t smem_u32(const void* p) {
    uint32_t a;
    asm("{ .reg .u64 t; cvta.to.shared.u64 t, %1; cvt.u32.u64 %0, t; }" : "=r"(a) : "l"(p));
    return a;
}
__device__ __forceinline__ void ldsm4(uint32_t* r, uint32_t addr) {
    asm volatile("ldmatrix.sync.aligned.m8n8.x4.shared.b16 {%0,%1,%2,%3}, [%4];"
                 : "=r"(r[0]), "=r"(r[1]), "=r"(r[2]), "=r"(r[3]) : "r"(addr));
}
__device__ __forceinline__ void ldsm4t(uint32_t* r, uint32_t addr) {
    asm volatile("ldmatrix.sync.aligned.m8n8.x4.trans.shared.b16 {%0,%1,%2,%3}, [%4];"
                 : "=r"(r[0]), "=r"(r[1]), "=r"(r[2]), "=r"(r[3]) : "r"(addr));
}
__device__ __forceinline__ void mma16816(float* c, const uint32_t* a, uint32_t b0, uint32_t b1) {
    asm volatile(
        "mma.sync.aligned.m16n8k16.row.col.f32.f16.f16.f32 "
        "{%0,%1,%2,%3}, {%4,%5,%6,%7}, {%8,%9}, {%0,%1,%2,%3};"
        : "+f"(c[0]), "+f"(c[1]), "+f"(c[2]), "+f"(c[3])
        : "r"(a[0]), "r"(a[1]), "r"(a[2]), "r"(a[3]), "r"(b0), "r"(b1));
}
__device__ __forceinline__ uint32_t packh(__half a, __half b) {
    __half2 t = __halves2half2(a, b);
    return *(uint32_t*)&t;
}
__device__ __forceinline__ float ex2f(float x) {
    float y;
    asm("ex2.approx.f32 %0, %1;" : "=f"(y) : "f"(x));
    return y;
}
__device__ __forceinline__ void cp16(uint32_t dst, const void* src) {
    asm volatile("cp.async.cg.shared.global [%0], [%1], 16;"
                 :: "r"(dst), "l"(__cvta_generic_to_global(src)) : "memory");
}
#define CP_COMMIT() asm volatile("cp.async.commit_group;" ::: "memory")
#define CP_WAIT0()  asm volatile("cp.async.wait_group 0;" ::: "memory")

// ============================================================================
// Kernel 0: weights fp32 -> fp16, stacked [Wk;Wq;Wv] = [192][512], 4/thread
// ============================================================================
__global__ void w16_kernel(const float* __restrict__ Wk, const float* __restrict__ Wq,
                           const float* __restrict__ Wv) {
    int i4 = (blockIdx.x * 256 + threadIdx.x) * 4;   // 0..98300
    const float* src;
    int off;
    if (i4 < 64 * EMBED)            { src = Wk; off = i4; }
    else if (i4 < 128 * EMBED)      { src = Wq; off = i4 - 64 * EMBED; }
    else                            { src = Wv; off = i4 - 128 * EMBED; }
    float4 f = *(const float4*)&src[off];
    uint2 h = make_uint2(packh(__float2half_rn(f.x), __float2half_rn(f.y)),
                         packh(__float2half_rn(f.z), __float2half_rn(f.w)));
    *(uint2*)&gW16[i4] = h;
}

// ============================================================================
// Kernel 1: KQV projection via fp16 mma.sync (single-precision-split-free).
// CTA: 64 rows x 192 cols, K-chunks of 64. 4 warps, warp = 16 m x 192 n.
// ============================================================================
#define PXS 0
#define PWS 8192

__global__ __launch_bounds__(128) void proj_mma(const float* __restrict__ x)
{
    __shared__ __align__(16) uint8_t smem[32768];
    const uint32_t sb = smem_u32(smem);

    const int tid  = threadIdx.x;
    const int wid  = tid >> 5;
    const int lane = tid & 31;
    const int m0w  = wid * 16;
    const int g    = lane >> 2;
    const int tg   = lane & 3;
    const int mblk = blockIdx.x * 64;

    float c[24][4];
#pragma unroll
    for (int j = 0; j < 24; j++)
#pragma unroll
        for (int q = 0; q < 4; q++) c[j][q] = 0.f;

    for (int kc = 0; kc < 8; kc++) {
        __syncthreads();
        // stage x chunk (64 rows x 64 k) fp32 -> fp16, swizzled
#pragma unroll
        for (int it = 0; it < 8; it++) {
            int idx = tid + it * 128;          // 0..1023 float4s
            int r = idx >> 4, c4 = idx & 15;
            float4 f = *(const float4*)&x[(size_t)(mblk + r) * EMBED + kc * 64 + c4 * 4];
            uint32_t dst = r * 128 + ((c4 * 8) ^ ((r & 7) << 4));
            *(uint2*)(smem + PXS + dst) =
                make_uint2(packh(__float2half_rn(f.x), __float2half_rn(f.y)),
                           packh(__float2half_rn(f.z), __float2half_rn(f.w)));
        }
        // stage W chunk (192 rows x 64 k fp16) via cp.async, swizzled
#pragma unroll
        for (int it = 0; it < 12; it++) {
            int idx = tid + it * 128;          // 0..1535 uint4s
            int r = idx >> 3, u = idx & 7;
            uint32_t dst = r * 128 + ((u * 16) ^ ((r & 7) << 4));
            cp16(sb + PWS + dst, &gW16[(size_t)r * EMBED + kc * 64 + u * 8]);
        }
        CP_COMMIT();
        CP_WAIT0();
        __syncthreads();

#pragma unroll
        for (int ks = 0; ks < 4; ks++) {
            uint32_t ah[4];
            int arow = m0w + (lane & 15);
            uint32_t abyte = (uint32_t)((ks * 32 + (lane >> 4) * 16) ^ ((arow & 7) << 4));
            ldsm4(ah, sb + PXS + arow * 128 + abyte);
#pragma unroll
            for (int jj = 0; jj < 12; jj++) {
                uint32_t b[4];
                int brow = jj * 16 + (lane & 7) + ((lane >> 4) << 3);
                uint32_t bby = (uint32_t)((ks * 32 + ((lane >> 3) & 1) * 16) ^ ((brow & 7) << 4));
                ldsm4(b, sb + PWS + brow * 128 + bby);
                mma16816(c[2 * jj],     ah, b[0], b[1]);
                mma16816(c[2 * jj + 1], ah, b[2], b[3]);
            }
        }
    }

    // epilogue: cols 0-63 -> K, 64-127 -> Q (scaled), 128-191 -> V
    const int m0 = mblk + m0w + g;
#pragma unroll
    for (int j = 0; j < 24; j++) {
        int col = j * 8 + 2 * tg;
        if (col < 64) {
            *(uint32_t*)&gK16[(size_t)m0 * HEAD + col] =
                packh(__float2half_rn(c[j][0]), __float2half_rn(c[j][1]));
            *(uint32_t*)&gK16[(size_t)(m0 + 8) * HEAD + col] =
                packh(__float2half_rn(c[j][2]), __float2half_rn(c[j][3]));
        } else if (col < 128) {
            int h = col - 64;
            *(uint32_t*)&gQ16[(size_t)m0 * HEAD + h] =
                packh(__float2half_rn(c[j][0] * QSC2), __float2half_rn(c[j][1] * QSC2));
            *(uint32_t*)&gQ16[(size_t)(m0 + 8) * HEAD + h] =
                packh(__float2half_rn(c[j][2] * QSC2), __float2half_rn(c[j][3] * QSC2));
        } else {
            int h = col - 128;
            *(uint32_t*)&gV16[(size_t)m0 * HEAD + h] =
                packh(__float2half_rn(c[j][0]), __float2half_rn(c[j][1]));
            *(uint32_t*)&gV16[(size_t)(m0 + 8) * HEAD + h] =
                packh(__float2half_rn(c[j][2]), __float2half_rn(c[j][3]));
        }
    }
}

// ============================================================================
// Kernel 2: causal flash attention via fp16 mma.sync + cp.async double buffer.
// CTA = 64 queries; 64-key tiles; 4 warps (warp = 16 q rows).
// No online max (scores bounded): l += sum(exp2), O += P @ V.
// ============================================================================
#define AQS  0            // 8KB  Q
#define AK0  8192         // 8KB  K buf0   (+8192 -> buf1)
#define AV0  24576        // 8KB  V buf0   (+8192 -> buf1)
#define APS  40960        // 8KB  P

__global__ __launch_bounds__(128, 3) void attn_mma(float* __restrict__ out)
{
    __shared__ __align__(16) uint8_t smem[49152];
    const uint32_t sb = smem_u32(smem);

    // load-balance mapping: first wave (bid 0..147) gets the big q-tiles
    const int bid = blockIdx.x;
    int rank;
    if (bid < 108)      rank = 40 + bid;
    else if (bid < 148) rank = bid - 108;
    else                rank = 255 - (bid - 148);
    const int qt = 63 - (rank >> 2);
    const int b  = rank & 3;

    const int tid  = threadIdx.x;
    const int wid  = tid >> 5;
    const int lane = tid & 31;
    const int m0w  = wid * 16;
    const int g    = lane >> 2;
    const int tg   = lane & 3;

    const __half* __restrict__ Qg = gQ16 + (size_t)(b * SEQ + qt * 64) * HEAD;
    const __half* __restrict__ Kb = gK16 + (size_t)(b * SEQ) * HEAD;
    const __half* __restrict__ Vb = gV16 + (size_t)(b * SEQ) * HEAD;

    // stage Q + tile 0 (K/V) via cp.async
#pragma unroll
    for (int it = 0; it < 4; it++) {
        int idx = tid + it * 128;          // 0..511
        int r = idx >> 3, u = idx & 7;
        uint32_t dst = r * 128 + ((u * 16) ^ ((r & 7) << 4));
        cp16(sb + AQS + dst, &Qg[r * HEAD + u * 8]);
        cp16(sb + AK0 + dst, &Kb[r * HEAD + u * 8]);
        cp16(sb + AV0 + dst, &Vb[r * HEAD + u * 8]);
    }
    CP_COMMIT();
    CP_WAIT0();
    __syncthreads();

    uint32_t qa[4][4];
    {
        int arow = m0w + (lane & 15);
#pragma unroll
        for (int k4 = 0; k4 < 4; k4++) {
            uint32_t abyte = (uint32_t)((k4 * 32 + (lane >> 4) * 16) ^ ((arow & 7) << 4));
            ldsm4(qa[k4], sb + AQS + arow * 128 + abyte);
        }
    }

    float oc[8][4];
#pragma unroll
    for (int j = 0; j < 8; j++)
#pragma unroll
        for (int q = 0; q < 4; q++) oc[j][q] = 0.f;
    float ls0 = 0.f, ls1 = 0.f;

    const int nkt = qt + 1;
    for (int kt = 0; kt < nkt; kt++) {
        // tile kt is resident (waited last iter / prologue); all warps synced
        // prefetch tile kt+1 into the other buffer
        if (kt + 1 < nkt) {
            uint32_t kbuf = AK0 + ((kt + 1) & 1) * 8192;
            uint32_t vbuf = AV0 + ((kt + 1) & 1) * 8192;
            const __half* Kg = Kb + (size_t)(kt + 1) * 64 * HEAD;
            const __half* Vg = Vb + (size_t)(kt + 1) * 64 * HEAD;
#pragma unroll
            for (int it = 0; it < 4; it++) {
                int idx = tid + it * 128;
                int r = idx >> 3, u = idx & 7;
                uint32_t dst = r * 128 + ((u * 16) ^ ((r & 7) << 4));
                cp16(sb + kbuf + dst, &Kg[r * HEAD + u * 8]);
                cp16(sb + vbuf + dst, &Vg[r * HEAD + u * 8]);
            }
            CP_COMMIT();
        }

        const uint32_t kbase = sb + AK0 + (kt & 1) * 8192;
        const uint32_t vbase = sb + AV0 + (kt & 1) * 8192;

        // ---- MMA1: S = Q @ K^T ----
        float sc[8][4];
#pragma unroll
        for (int j = 0; j < 8; j++)
#pragma unroll
            for (int q = 0; q < 4; q++) sc[j][q] = 0.f;
#pragma unroll
        for (int jj = 0; jj < 4; jj++) {
            int brow = jj * 16 + (lane & 7) + ((lane >> 4) << 3);
#pragma unroll
            for (int k4 = 0; k4 < 4; k4++) {
                uint32_t bby = (uint32_t)((k4 * 32 + ((lane >> 3) & 1) * 16) ^ ((brow & 7) << 4));
                uint32_t bk[4];
                ldsm4(bk, kbase + brow * 128 + bby);
                mma16816(sc[2 * jj],     qa[k4], bk[0], bk[1]);
                mma16816(sc[2 * jj + 1], qa[k4], bk[2], bk[3]);
            }
        }

        // ---- mask + exp2 + P store (warp-private rows) ----
        const bool diag = (kt == qt);
        const int lr0 = m0w + g, lr1 = lr0 + 8;
#pragma unroll
        for (int jn = 0; jn < 8; jn++) {
            int c0 = jn * 8 + 2 * tg;
            float p0, p1, p2, p3;
            if (diag) {
                p0 = (c0     <= lr0) ? ex2f(sc[jn][0]) : 0.f;
                p1 = (c0 + 1 <= lr0) ? ex2f(sc[jn][1]) : 0.f;
                p2 = (c0     <= lr1) ? ex2f(sc[jn][2]) : 0.f;
                p3 = (c0 + 1 <= lr1) ? ex2f(sc[jn][3]) : 0.f;
            } else {
                p0 = ex2f(sc[jn][0]); p1 = ex2f(sc[jn][1]);
                p2 = ex2f(sc[jn][2]); p3 = ex2f(sc[jn][3]);
            }
            ls0 += p0 + p1;
            ls1 += p2 + p3;
            *(uint32_t*)(smem + APS + lr0 * 128 + ((c0 * 2) ^ ((lr0 & 7) << 4))) =
                packh(__float2half_rn(p0), __float2half_rn(p1));
            *(uint32_t*)(smem + APS + lr1 * 128 + ((c0 * 2) ^ ((lr1 & 7) << 4))) =
                packh(__float2half_rn(p2), __float2half_rn(p3));
        }
        __syncwarp();

        // ---- MMA2: O += P @ V ----
        uint32_t pa[4][4];
        {
            int arow = m0w + (lane & 15);
#pragma unroll
            for (int k4 = 0; k4 < 4; k4++) {
                uint32_t abyte = (uint32_t)((k4 * 32 + (lane >> 4) * 16) ^ ((arow & 7) << 4));
                ldsm4(pa[k4], sb + APS + arow * 128 + abyte);
            }
        }
#pragma unroll
        for (int jj = 0; jj < 4; jj++) {
#pragma unroll
            for (int k4 = 0; k4 < 4; k4++) {
                int krow = k4 * 16 + (lane & 7) + (((lane >> 3) & 1) << 3);
                uint32_t vby = (uint32_t)(((jj * 16 + ((lane >> 4) << 3)) * 2) ^ ((krow & 7) << 4));
                uint32_t bv[4];
                ldsm4t(bv, vbase + krow * 128 + vby);
                mma16816(oc[2 * jj],     pa[k4], bv[0], bv[1]);
                mma16816(oc[2 * jj + 1], pa[k4], bv[2], bv[3]);
            }
        }

        // wait for prefetched tile + make buffers safe to overwrite next iter
        if (kt + 1 < nkt) {
            CP_WAIT0();
            __syncthreads();
        }
    }

    // ---- epilogue ----
    ls0 += __shfl_xor_sync(0xffffffffu, ls0, 1);
    ls0 += __shfl_xor_sync(0xffffffffu, ls0, 2);
    ls1 += __shfl_xor_sync(0xffffffffu, ls1, 1);
    ls1 += __shfl_xor_sync(0xffffffffu, ls1, 2);
    const float inv0 = 1.0f / ls0;
    const float inv1 = 1.0f / ls1;

    const size_t ro = (size_t)(b * SEQ + qt * 64 + m0w + g) * HEAD;
#pragma unroll
    for (int jn = 0; jn < 8; jn++) {
        int col = jn * 8 + 2 * tg;
        float2 v0 = make_float2(oc[jn][0] * inv0, oc[jn][1] * inv0);
        float2 v1 = make_float2(oc[jn][2] * inv1, oc[jn][3] * inv1);
        *(float2*)&out[ro + col]            = v0;
        *(float2*)&out[ro + 8 * HEAD + col] = v1;
    }
}

// ============================================================================
// launch
// ============================================================================
extern "C" void kernel_launch(void* const* d_in, const int* in_sizes, int n_in,
                              void* d_out, int out_size)
{
    const float* x  = (const float*)d_in[0];
    const float* Wk = (const float*)d_in[1];
    const float* Wq = (const float*)d_in[2];
    const float* Wv = (const float*)d_in[3];
    float* out = (float*)d_out;

    w16_kernel<<<96, 256>>>(Wk, Wq, Wv);
    proj_mma<<<NTOK / 64, 128>>>(x);
    attn_mma<<<256, 128>>>(out);
}

// round 5
// speedup vs baseline: 7.9077x; 1.1474x over previous
#include <cuda_runtime.h>
#include <cuda_fp16.h>
#include <cstdint>

#define BATCH 4
#define SEQ   4096
#define EMBED 512
#define HEAD  64
#define NTOK  (BATCH * SEQ)
// C^-0.5 * log2(e): Q pre-scale so softmax uses raw ex2
#define QSC2  (0.04419417382415922f * 1.4426950408889634f)

// ---------------- scratch (device globals) ----------------
__device__ __half gK16[NTOK * HEAD];   // [t][h]
__device__ __half gQ16[NTOK * HEAD];   // [t][h], pre-scaled by QSC2
__device__ __half gV16[NTOK * HEAD];   // [t][h]

// ---------------- helpers ----------------
__device__ __forceinline__ uint32_t smem_u32(const void* p) {
    uint32_t a;
    asm("{ .reg .u64 t; cvta.to.shared.u64 t, %1; cvt.u32.u64 %0, t; }" : "=r"(a) : "l"(p));
    return a;
}
__device__ __forceinline__ void ldsm4(uint32_t* r, uint32_t addr) {
    asm volatile("ldmatrix.sync.aligned.m8n8.x4.shared.b16 {%0,%1,%2,%3}, [%4];"
                 : "=r"(r[0]), "=r"(r[1]), "=r"(r[2]), "=r"(r[3]) : "r"(addr));
}
__device__ __forceinline__ void ldsm4t(uint32_t* r, uint32_t addr) {
    asm volatile("ldmatrix.sync.aligned.m8n8.x4.trans.shared.b16 {%0,%1,%2,%3}, [%4];"
                 : "=r"(r[0]), "=r"(r[1]), "=r"(r[2]), "=r"(r[3]) : "r"(addr));
}
__device__ __forceinline__ void mma16816(float* c, const uint32_t* a, uint32_t b0, uint32_t b1) {
    asm volatile(
        "mma.sync.aligned.m16n8k16.row.col.f32.f16.f16.f32 "
        "{%0,%1,%2,%3}, {%4,%5,%6,%7}, {%8,%9}, {%0,%1,%2,%3};"
        : "+f"(c[0]), "+f"(c[1]), "+f"(c[2]), "+f"(c[3])
        : "r"(a[0]), "r"(a[1]), "r"(a[2]), "r"(a[3]), "r"(b0), "r"(b1));
}
__device__ __forceinline__ uint32_t packh(__half a, __half b) {
    __half2 t = __halves2half2(a, b);
    return *(uint32_t*)&t;
}
__device__ __forceinline__ float ex2f(float x) {
    float y;
    asm("ex2.approx.f32 %0, %1;" : "=f"(y) : "f"(x));
    return y;
}
__device__ __forceinline__ void cp16(uint32_t dst, const void* src) {
    asm volatile("cp.async.cg.shared.global [%0], [%1], 16;"
                 :: "r"(dst), "l"(__cvta_generic_to_global(src)) : "memory");
}
#define CP_COMMIT() asm volatile("cp.async.commit_group;" ::: "memory")
#define CP_WAIT0()  asm volatile("cp.async.wait_group 0;" ::: "memory")
#define BARG(id)    asm volatile("bar.sync %0, 128;" :: "r"(id) : "memory")

// ============================================================================
// Kernel 1: KQV projection via fp16 mma.sync. 256 threads, 8 warps.
// CTA: 64 rows x 192 cols, K-chunks of 64. Warp (h = wid>>2) covers
// rows (wid&3)*16, cols h*96. W converted fp32->fp16 during staging.
// ============================================================================
#define PXS 0
#define PWS 8192

__global__ __launch_bounds__(256) void proj_mma(
    const float* __restrict__ x, const float* __restrict__ Wk,
    const float* __restrict__ Wq, const float* __restrict__ Wv)
{
    __shared__ __align__(16) uint8_t smem[32768];
    const uint32_t sb = smem_u32(smem);

    const int tid  = threadIdx.x;
    const int wid  = tid >> 5;
    const int lane = tid & 31;
    const int wm   = (wid & 3) * 16;    // warp row base
    const int h    = wid >> 2;          // warp n-half (0: cols 0-95, 1: 96-191)
    const int g    = lane >> 2;
    const int tg   = lane & 3;
    const int mblk = blockIdx.x * 64;

    float c[12][4];
#pragma unroll
    for (int j = 0; j < 12; j++)
#pragma unroll
        for (int q = 0; q < 4; q++) c[j][q] = 0.f;

    for (int kc = 0; kc < 8; kc++) {
        __syncthreads();
        // stage x chunk (64 rows x 64 k) fp32 -> fp16, swizzled
#pragma unroll
        for (int it = 0; it < 4; it++) {
            int idx = tid + it * 256;          // 0..1023 float4s
            int r = idx >> 4, c4 = idx & 15;
            float4 f = *(const float4*)&x[(size_t)(mblk + r) * EMBED + kc * 64 + c4 * 4];
            uint32_t dst = r * 128 + ((c4 * 8) ^ ((r & 7) << 4));
            *(uint2*)(smem + PXS + dst) =
                make_uint2(packh(__float2half_rn(f.x), __float2half_rn(f.y)),
                           packh(__float2half_rn(f.z), __float2half_rn(f.w)));
        }
        // stage W chunk (192 rows x 64 k) fp32 -> fp16, swizzled
#pragma unroll
        for (int it = 0; it < 12; it++) {
            int idx = tid + it * 256;          // 0..3071 float4s
            int r = idx >> 4, c4 = idx & 15;
            const float* src = (r < 64) ? &Wk[(size_t)r * EMBED]
                             : (r < 128) ? &Wq[(size_t)(r - 64) * EMBED]
                                         : &Wv[(size_t)(r - 128) * EMBED];
            float4 f = *(const float4*)&src[kc * 64 + c4 * 4];
            uint32_t dst = r * 128 + ((c4 * 8) ^ ((r & 7) << 4));
            *(uint2*)(smem + PWS + dst) =
                make_uint2(packh(__float2half_rn(f.x), __float2half_rn(f.y)),
                           packh(__float2half_rn(f.z), __float2half_rn(f.w)));
        }
        __syncthreads();

#pragma unroll
        for (int ks = 0; ks < 4; ks++) {
            uint32_t ah[4];
            int arow = wm + (lane & 15);
            uint32_t abyte = (uint32_t)((ks * 32 + (lane >> 4) * 16) ^ ((arow & 7) << 4));
            ldsm4(ah, sb + PXS + arow * 128 + abyte);
#pragma unroll
            for (int jj = 0; jj < 6; jj++) {
                uint32_t b[4];
                int brow = h * 96 + jj * 16 + (lane & 7) + ((lane >> 4) << 3);
                uint32_t bby = (uint32_t)((ks * 32 + ((lane >> 3) & 1) * 16) ^ ((brow & 7) << 4));
                ldsm4(b, sb + PWS + brow * 128 + bby);
                mma16816(c[2 * jj],     ah, b[0], b[1]);
                mma16816(c[2 * jj + 1], ah, b[2], b[3]);
            }
        }
    }

    // epilogue: global col = h*96 + j*8 + 2tg; 0-63 K, 64-127 Q (scaled), 128-191 V
    const int m0 = mblk + wm + g;
#pragma unroll
    for (int j = 0; j < 12; j++) {
        int col = h * 96 + j * 8 + 2 * tg;
        if (col < 64) {
            *(uint32_t*)&gK16[(size_t)m0 * HEAD + col] =
                packh(__float2half_rn(c[j][0]), __float2half_rn(c[j][1]));
            *(uint32_t*)&gK16[(size_t)(m0 + 8) * HEAD + col] =
                packh(__float2half_rn(c[j][2]), __float2half_rn(c[j][3]));
        } else if (col < 128) {
            int hh = col - 64;
            *(uint32_t*)&gQ16[(size_t)m0 * HEAD + hh] =
                packh(__float2half_rn(c[j][0] * QSC2), __float2half_rn(c[j][1] * QSC2));
            *(uint32_t*)&gQ16[(size_t)(m0 + 8) * HEAD + hh] =
                packh(__float2half_rn(c[j][2] * QSC2), __float2half_rn(c[j][3] * QSC2));
        } else {
            int hh = col - 128;
            *(uint32_t*)&gV16[(size_t)m0 * HEAD + hh] =
                packh(__float2half_rn(c[j][0]), __float2half_rn(c[j][1]));
            *(uint32_t*)&gV16[(size_t)(m0 + 8) * HEAD + hh] =
                packh(__float2half_rn(c[j][2]), __float2half_rn(c[j][3]));
        }
    }
}

// ============================================================================
// Kernel 2: causal flash attention, 256 threads = 2 key-parity groups x 4 warps.
// Group 0: even key tiles, group 1: odd. Each group: own double-buffered K/V
// (cp.async) + own P buffer, synced by named barriers. Partials combined via
// smem at the end. No online max: l += sum(exp2), O += P @ V.
// ============================================================================
// dynamic smem layout (bytes):
#define AQS   0            // 8KB Q
#define AKB   8192         // 4x8KB: K[group][stage]
#define AVB   40960        // 4x8KB: V[group][stage]
#define APS   73728        // 2x8KB: P[group]   (reused as 16KB O-exchange)
#define ALX   90112        // 256B  l-exchange
#define ASMEM 90368

__global__ __launch_bounds__(256, 2) void attn_mma(float* __restrict__ out)
{
    extern __shared__ __align__(16) uint8_t smem[];
    const uint32_t sb = smem_u32(smem);

    // load-balance mapping: first wave (bid 0..147) gets the big q-tiles
    const int bid = blockIdx.x;
    int rank;
    if (bid < 108)      rank = 40 + bid;
    else if (bid < 148) rank = bid - 108;
    else                rank = 255 - (bid - 148);
    const int qt = 63 - (rank >> 2);
    const int b  = rank & 3;

    const int tid  = threadIdx.x;
    const int wid  = tid >> 5;
    const int lane = tid & 31;
    const int gid  = wid >> 2;          // key-parity group
    const int m0w  = (wid & 3) * 16;    // warp's query-row base
    const int g    = lane >> 2;
    const int tg   = lane & 3;
    const int gtid = tid & 127;

    const __half* __restrict__ Qg = gQ16 + (size_t)(b * SEQ + qt * 64) * HEAD;
    const __half* __restrict__ Kb = gK16 + (size_t)(b * SEQ) * HEAD;
    const __half* __restrict__ Vb = gV16 + (size_t)(b * SEQ) * HEAD;

    const uint32_t KB0 = AKB + gid * 16384;   // this group's K stage-0
    const uint32_t VB0 = AVB + gid * 16384;
    const uint32_t PB  = APS + gid * 8192;

    // stage Q (all 256 threads) + first tile per group
#pragma unroll
    for (int it = 0; it < 2; it++) {
        int idx = tid + it * 256;          // 0..511
        int r = idx >> 3, u = idx & 7;
        uint32_t dst = r * 128 + ((u * 16) ^ ((r & 7) << 4));
        cp16(sb + AQS + dst, &Qg[r * HEAD + u * 8]);
    }
    if (gid <= qt) {
        const __half* Kg = Kb + (size_t)gid * 64 * HEAD;
        const __half* Vg = Vb + (size_t)gid * 64 * HEAD;
#pragma unroll
        for (int it = 0; it < 4; it++) {
            int idx = gtid + it * 128;
            int r = idx >> 3, u = idx & 7;
            uint32_t dst = r * 128 + ((u * 16) ^ ((r & 7) << 4));
            cp16(sb + KB0 + dst, &Kg[r * HEAD + u * 8]);
            cp16(sb + VB0 + dst, &Vg[r * HEAD + u * 8]);
        }
    }
    CP_COMMIT();
    CP_WAIT0();
    __syncthreads();

    uint32_t qa[4][4];
    {
        int arow = m0w + (lane & 15);
#pragma unroll
        for (int k4 = 0; k4 < 4; k4++) {
            uint32_t abyte = (uint32_t)((k4 * 32 + (lane >> 4) * 16) ^ ((arow & 7) << 4));
            ldsm4(qa[k4], sb + AQS + arow * 128 + abyte);
        }
    }

    float oc[8][4];
#pragma unroll
    for (int j = 0; j < 8; j++)
#pragma unroll
        for (int q = 0; q < 4; q++) oc[j][q] = 0.f;
    float ls0 = 0.f, ls1 = 0.f;

    int stage = 0;
    for (int kt = gid; kt <= qt; kt += 2) {
        // prefetch tile kt+2 into other stage
        if (kt + 2 <= qt) {
            uint32_t kbuf = KB0 + (stage ^ 1) * 8192;
            uint32_t vbuf = VB0 + (stage ^ 1) * 8192;
            const __half* Kg = Kb + (size_t)(kt + 2) * 64 * HEAD;
            const __half* Vg = Vb + (size_t)(kt + 2) * 64 * HEAD;
#pragma unroll
            for (int it = 0; it < 4; it++) {
                int idx = gtid + it * 128;
                int r = idx >> 3, u = idx & 7;
                uint32_t dst = r * 128 + ((u * 16) ^ ((r & 7) << 4));
                cp16(sb + kbuf + dst, &Kg[r * HEAD + u * 8]);
                cp16(sb + vbuf + dst, &Vg[r * HEAD + u * 8]);
            }
            CP_COMMIT();
        }

        const uint32_t kbase = sb + KB0 + stage * 8192;
        const uint32_t vbase = sb + VB0 + stage * 8192;

        // ---- MMA1: S = Q @ K^T ----
        float sc[8][4];
#pragma unroll
        for (int j = 0; j < 8; j++)
#pragma unroll
            for (int q = 0; q < 4; q++) sc[j][q] = 0.f;
#pragma unroll
        for (int jj = 0; jj < 4; jj++) {
            int brow = jj * 16 + (lane & 7) + ((lane >> 4) << 3);
#pragma unroll
            for (int k4 = 0; k4 < 4; k4++) {
                uint32_t bby = (uint32_t)((k4 * 32 + ((lane >> 3) & 1) * 16) ^ ((brow & 7) << 4));
                uint32_t bk[4];
                ldsm4(bk, kbase + brow * 128 + bby);
                mma16816(sc[2 * jj],     qa[k4], bk[0], bk[1]);
                mma16816(sc[2 * jj + 1], qa[k4], bk[2], bk[3]);
            }
        }

        // ---- mask + exp2 + P store (warp-private rows) ----
        const bool diag = (kt == qt);
        const int lr0 = m0w + g, lr1 = lr0 + 8;
#pragma unroll
        for (int jn = 0; jn < 8; jn++) {
            int c0 = jn * 8 + 2 * tg;
            float p0, p1, p2, p3;
            if (diag) {
                p0 = (c0     <= lr0) ? ex2f(sc[jn][0]) : 0.f;
                p1 = (c0 + 1 <= lr0) ? ex2f(sc[jn][1]) : 0.f;
                p2 = (c0     <= lr1) ? ex2f(sc[jn][2]) : 0.f;
                p3 = (c0 + 1 <= lr1) ? ex2f(sc[jn][3]) : 0.f;
            } else {
                p0 = ex2f(sc[jn][0]); p1 = ex2f(sc[jn][1]);
                p2 = ex2f(sc[jn][2]); p3 = ex2f(sc[jn][3]);
            }
            ls0 += p0 + p1;
            ls1 += p2 + p3;
            *(uint32_t*)(smem + PB + lr0 * 128 + ((c0 * 2) ^ ((lr0 & 7) << 4))) =
                packh(__float2half_rn(p0), __float2half_rn(p1));
            *(uint32_t*)(smem + PB + lr1 * 128 + ((c0 * 2) ^ ((lr1 & 7) << 4))) =
                packh(__float2half_rn(p2), __float2half_rn(p3));
        }
        __syncwarp();

        // ---- MMA2: O += P @ V ----
        uint32_t pa[4][4];
        {
            int arow = m0w + (lane & 15);
#pragma unroll
            for (int k4 = 0; k4 < 4; k4++) {
                uint32_t abyte = (uint32_t)((k4 * 32 + (lane >> 4) * 16) ^ ((arow & 7) << 4));
                ldsm4(pa[k4], sb + PB + arow * 128 + abyte);
            }
        }
#pragma unroll
        for (int jj = 0; jj < 4; jj++) {
#pragma unroll
            for (int k4 = 0; k4 < 4; k4++) {
                int krow = k4 * 16 + (lane & 7) + (((lane >> 3) & 1) << 3);
                uint32_t vby = (uint32_t)(((jj * 16 + ((lane >> 4) << 3)) * 2) ^ ((krow & 7) << 4));
                uint32_t bv[4];
                ldsm4t(bv, vbase + krow * 128 + vby);
                mma16816(oc[2 * jj],     pa[k4], bv[0], bv[1]);
                mma16816(oc[2 * jj + 1], pa[k4], bv[2], bv[3]);
            }
        }

        if (kt + 2 <= qt) {
            CP_WAIT0();
            BARG(1 + gid);    // group barrier: buffers safe + staged data visible
        }
        stage ^= 1;
    }

    // ---- reduce l within quads ----
    ls0 += __shfl_xor_sync(0xffffffffu, ls0, 1);
    ls0 += __shfl_xor_sync(0xffffffffu, ls0, 2);
    ls1 += __shfl_xor_sync(0xffffffffu, ls1, 1);
    ls1 += __shfl_xor_sync(0xffffffffu, ls1, 2);

    // ---- cross-group combine ----
    __syncthreads();
    float* Oex = (float*)(smem + APS);
    float* lx  = (float*)(smem + ALX);
    const int lr0 = m0w + g, lr1 = lr0 + 8;
    if (gid == 1) {
#pragma unroll
        for (int jn = 0; jn < 8; jn++) {
            int col = jn * 8 + 2 * tg;
            *(float2*)&Oex[lr0 * 64 + col] = make_float2(oc[jn][0], oc[jn][1]);
            *(float2*)&Oex[lr1 * 64 + col] = make_float2(oc[jn][2], oc[jn][3]);
        }
        if (tg == 0) { lx[lr0] = ls0; lx[lr1] = ls1; }
    }
    __syncthreads();
    if (gid == 0) {
        const float inv0 = 1.0f / (ls0 + lx[lr0]);
        const float inv1 = 1.0f / (ls1 + lx[lr1]);
        const size_t ro = (size_t)(b * SEQ + qt * 64 + lr0) * HEAD;
#pragma unroll
        for (int jn = 0; jn < 8; jn++) {
            int col = jn * 8 + 2 * tg;
            float2 e0 = *(float2*)&Oex[lr0 * 64 + col];
            float2 e1 = *(float2*)&Oex[lr1 * 64 + col];
            float2 v0 = make_float2((oc[jn][0] + e0.x) * inv0, (oc[jn][1] + e0.y) * inv0);
            float2 v1 = make_float2((oc[jn][2] + e1.x) * inv1, (oc[jn][3] + e1.y) * inv1);
            *(float2*)&out[ro + col]            = v0;
            *(float2*)&out[ro + 8 * HEAD + col] = v1;
        }
    }
}

// ============================================================================
// launch
// ============================================================================
extern "C" void kernel_launch(void* const* d_in, const int* in_sizes, int n_in,
                              void* d_out, int out_size)
{
    const float* x  = (const float*)d_in[0];
    const float* Wk = (const float*)d_in[1];
    const float* Wq = (const float*)d_in[2];
    const float* Wv = (const float*)d_in[3];
    float* out = (float*)d_out;

    proj_mma<<<NTOK / 64, 256>>>(x, Wk, Wq, Wv);

    cudaFuncSetAttribute(attn_mma, cudaFuncAttributeMaxDynamicSharedMemorySize, ASMEM);
    attn_mma<<<256, 256, ASMEM>>>(out);
}

// round 6
// speedup vs baseline: 9.1719x; 1.1599x over previous
#include <cuda_runtime.h>
#include <cuda_fp16.h>
#include <cstdint>

#define BATCH 4
#define SEQ   4096
#define EMBED 512
#define HEAD  64
#define NTOK  (BATCH * SEQ)
// C^-0.5 * log2(e): Q pre-scale so softmax uses raw ex2
#define QSC2  (0.04419417382415922f * 1.4426950408889634f)

#define NUNITS 640          // split-K work units (160 per batch)

// ---------------- scratch (device globals) ----------------
__device__ __half gK16[NTOK * HEAD];   // [t][h]
__device__ __half gQ16[NTOK * HEAD];   // [t][h], pre-scaled by QSC2
__device__ __half gV16[NTOK * HEAD];   // [t][h]
__device__ float  gOp[NUNITS * 64 * 64];  // partial O (unnormalized)
__device__ float  gLp[NUNITS * 64];       // partial l

// ---------------- helpers ----------------
__device__ __forceinline__ uint32_t smem_u32(const void* p) {
    uint32_t a;
    asm("{ .reg .u64 t; cvta.to.shared.u64 t, %1; cvt.u32.u64 %0, t; }" : "=r"(a) : "l"(p));
    return a;
}
__device__ __forceinline__ void ldsm4(uint32_t* r, uint32_t addr) {
    asm volatile("ldmatrix.sync.aligned.m8n8.x4.shared.b16 {%0,%1,%2,%3}, [%4];"
                 : "=r"(r[0]), "=r"(r[1]), "=r"(r[2]), "=r"(r[3]) : "r"(addr));
}
__device__ __forceinline__ void ldsm4t(uint32_t* r, uint32_t addr) {
    asm volatile("ldmatrix.sync.aligned.m8n8.x4.trans.shared.b16 {%0,%1,%2,%3}, [%4];"
                 : "=r"(r[0]), "=r"(r[1]), "=r"(r[2]), "=r"(r[3]) : "r"(addr));
}
__device__ __forceinline__ void mma16816(float* c, const uint32_t* a, uint32_t b0, uint32_t b1) {
    asm volatile(
        "mma.sync.aligned.m16n8k16.row.col.f32.f16.f16.f32 "
        "{%0,%1,%2,%3}, {%4,%5,%6,%7}, {%8,%9}, {%0,%1,%2,%3};"
        : "+f"(c[0]), "+f"(c[1]), "+f"(c[2]), "+f"(c[3])
        : "r"(a[0]), "r"(a[1]), "r"(a[2]), "r"(a[3]), "r"(b0), "r"(b1));
}
__device__ __forceinline__ uint32_t packh(__half a, __half b) {
    __half2 t = __halves2half2(a, b);
    return *(uint32_t*)&t;
}
__device__ __forceinline__ float ex2f(float x) {
    float y;
    asm("ex2.approx.f32 %0, %1;" : "=f"(y) : "f"(x));
    return y;
}
__device__ __forceinline__ void cp16(uint32_t dst, const void* src) {
    asm volatile("cp.async.cg.shared.global [%0], [%1], 16;"
                 :: "r"(dst), "l"(__cvta_generic_to_global(src)) : "memory");
}
#define CP_COMMIT() asm volatile("cp.async.commit_group;" ::: "memory")
#define CP_WAIT0()  asm volatile("cp.async.wait_group 0;" ::: "memory")

// ============================================================================
// Kernel 1: KQV projection via fp16 mma.sync, double-buffered staging.
// CTA: 64 rows x 192 cols, 256 threads = 8 warps: warp (h=wid>>2) covers
// rows (wid&3)*16, cols h*96. One __syncthreads per 64-K chunk.
// ============================================================================
#define PX(s) ((s) * 8192)             // 2 x 8KB x buffers
#define PW(s) (16384 + (s) * 24576)    // 2 x 24KB W buffers
#define PSMEM 65536

__global__ __launch_bounds__(256) void proj_mma(
    const float* __restrict__ x, const float* __restrict__ Wk,
    const float* __restrict__ Wq, const float* __restrict__ Wv)
{
    extern __shared__ __align__(16) uint8_t smem[];
    const uint32_t sb = smem_u32(smem);

    const int tid  = threadIdx.x;
    const int wid  = tid >> 5;
    const int lane = tid & 31;
    const int wm   = (wid & 3) * 16;    // warp row base
    const int h    = wid >> 2;          // warp n-half (0: cols 0-95, 1: 96-191)
    const int g    = lane >> 2;
    const int tg   = lane & 3;
    const int mblk = blockIdx.x * 64;

    float c[12][4];
#pragma unroll
    for (int j = 0; j < 12; j++)
#pragma unroll
        for (int q = 0; q < 4; q++) c[j][q] = 0.f;

    // ---- staging lambda-ish macros (x: 64x64, W: 192x64, fp32->fp16) ----
#define STAGE_CHUNK(kc, s)                                                          \
    do {                                                                            \
        _Pragma("unroll")                                                           \
        for (int it = 0; it < 4; it++) {                                            \
            int idx = tid + it * 256;                                               \
            int r = idx >> 4, c4 = idx & 15;                                        \
            float4 f = *(const float4*)&x[(size_t)(mblk + r) * EMBED + (kc) * 64 + c4 * 4]; \
            uint32_t dst = r * 128 + ((c4 * 8) ^ ((r & 7) << 4));                   \
            *(uint2*)(smem + PX(s) + dst) =                                         \
                make_uint2(packh(__float2half_rn(f.x), __float2half_rn(f.y)),       \
                           packh(__float2half_rn(f.z), __float2half_rn(f.w)));      \
        }                                                                           \
        _Pragma("unroll")                                                           \
        for (int it = 0; it < 12; it++) {                                           \
            int idx = tid + it * 256;                                               \
            int r = idx >> 4, c4 = idx & 15;                                        \
            const float* src = (r < 64) ? &Wk[(size_t)r * EMBED]                    \
                             : (r < 128) ? &Wq[(size_t)(r - 64) * EMBED]            \
                                         : &Wv[(size_t)(r - 128) * EMBED];          \
            float4 f = *(const float4*)&src[(kc) * 64 + c4 * 4];                    \
            uint32_t dst = r * 128 + ((c4 * 8) ^ ((r & 7) << 4));                   \
            *(uint2*)(smem + PW(s) + dst) =                                         \
                make_uint2(packh(__float2half_rn(f.x), __float2half_rn(f.y)),       \
                           packh(__float2half_rn(f.z), __float2half_rn(f.w)));      \
        }                                                                           \
    } while (0)

    STAGE_CHUNK(0, 0);
    __syncthreads();

    for (int kc = 0; kc < 8; kc++) {
        const int s = kc & 1;
        if (kc < 7) STAGE_CHUNK(kc + 1, s ^ 1);

#pragma unroll
        for (int ks = 0; ks < 4; ks++) {
            uint32_t ah[4];
            int arow = wm + (lane & 15);
            uint32_t abyte = (uint32_t)((ks * 32 + (lane >> 4) * 16) ^ ((arow & 7) << 4));
            ldsm4(ah, sb + PX(s) + arow * 128 + abyte);
#pragma unroll
            for (int jj = 0; jj < 6; jj++) {
                uint32_t b[4];
                int brow = h * 96 + jj * 16 + (lane & 7) + ((lane >> 4) << 3);
                uint32_t bby = (uint32_t)((ks * 32 + ((lane >> 3) & 1) * 16) ^ ((brow & 7) << 4));
                ldsm4(b, sb + PW(s) + brow * 128 + bby);
                mma16816(c[2 * jj],     ah, b[0], b[1]);
                mma16816(c[2 * jj + 1], ah, b[2], b[3]);
            }
        }
        __syncthreads();
    }

    // epilogue: global col = h*96 + j*8 + 2tg; 0-63 K, 64-127 Q (scaled), 128-191 V
    const int m0 = mblk + wm + g;
#pragma unroll
    for (int j = 0; j < 12; j++) {
        int col = h * 96 + j * 8 + 2 * tg;
        if (col < 64) {
            *(uint32_t*)&gK16[(size_t)m0 * HEAD + col] =
                packh(__float2half_rn(c[j][0]), __float2half_rn(c[j][1]));
            *(uint32_t*)&gK16[(size_t)(m0 + 8) * HEAD + col] =
                packh(__float2half_rn(c[j][2]), __float2half_rn(c[j][3]));
        } else if (col < 128) {
            int hh = col - 64;
            *(uint32_t*)&gQ16[(size_t)m0 * HEAD + hh] =
                packh(__float2half_rn(c[j][0] * QSC2), __float2half_rn(c[j][1] * QSC2));
            *(uint32_t*)&gQ16[(size_t)(m0 + 8) * HEAD + hh] =
                packh(__float2half_rn(c[j][2] * QSC2), __float2half_rn(c[j][3] * QSC2));
        } else {
            int hh = col - 128;
            *(uint32_t*)&gV16[(size_t)m0 * HEAD + hh] =
                packh(__float2half_rn(c[j][0]), __float2half_rn(c[j][1]));
            *(uint32_t*)&gV16[(size_t)(m0 + 8) * HEAD + hh] =
                packh(__float2half_rn(c[j][2]), __float2half_rn(c[j][3]));
        }
    }
#undef STAGE_CHUNK
}

// ============================================================================
// Kernel 2a: attention pass 1 (split-K). Unit = (b, 64-q-tile, <=16 key tiles).
// 128 threads, 4 warps; cp.async double-buffered K/V. Writes unnormalized
// partial O (fp32 64x64) + partial l (64) to gmem.
// Unit offsets within a batch (160 total):
//   qt in [0,16):  1 chunk  -> off = qt
//   qt in [16,32): 2 chunks -> off = 16 + (qt-16)*2 + c
//   qt in [32,48): 3 chunks -> off = 48 + (qt-32)*3 + c
//   qt in [48,64): 4 chunks -> off = 96 + (qt-48)*4 + c
// ============================================================================
#define AQS  0            // 8KB Q
#define AK0  8192         // 2x8KB K
#define AV0  24576        // 2x8KB V
#define APS  40960        // 8KB P

__global__ __launch_bounds__(128, 4) void attn_part(void)
{
    __shared__ __align__(16) uint8_t smem[49152];
    const uint32_t sb = smem_u32(smem);

    // big-qt units first
    const int slot = (NUNITS - 1) - blockIdx.x;
    const int b = slot / 160;
    const int r = slot % 160;
    int qt, ch;
    if (r < 16)      { qt = r;                 ch = 0; }
    else if (r < 48) { qt = 16 + ((r - 16) >> 1); ch = (r - 16) & 1; }
    else if (r < 96) { qt = 32 + (r - 48) / 3;    ch = (r - 48) % 3; }
    else             { qt = 48 + ((r - 96) >> 2); ch = (r - 96) & 3; }
    const int kt0 = ch * 16;
    const int kt1 = (kt0 + 16 < qt + 1) ? (kt0 + 16) : (qt + 1);

    const int tid  = threadIdx.x;
    const int wid  = tid >> 5;
    const int lane = tid & 31;
    const int m0w  = wid * 16;
    const int g    = lane >> 2;
    const int tg   = lane & 3;

    const __half* __restrict__ Qg = gQ16 + (size_t)(b * SEQ + qt * 64) * HEAD;
    const __half* __restrict__ Kb = gK16 + (size_t)(b * SEQ) * HEAD;
    const __half* __restrict__ Vb = gV16 + (size_t)(b * SEQ) * HEAD;

    // stage Q + first K/V tile
#pragma unroll
    for (int it = 0; it < 4; it++) {
        int idx = tid + it * 128;          // 0..511
        int rr = idx >> 3, u = idx & 7;
        uint32_t dst = rr * 128 + ((u * 16) ^ ((rr & 7) << 4));
        cp16(sb + AQS + dst, &Qg[rr * HEAD + u * 8]);
        cp16(sb + AK0 + dst, &Kb[(size_t)(kt0 * 64 + rr) * HEAD + u * 8]);
        cp16(sb + AV0 + dst, &Vb[(size_t)(kt0 * 64 + rr) * HEAD + u * 8]);
    }
    CP_COMMIT();
    CP_WAIT0();
    __syncthreads();

    uint32_t qa[4][4];
    {
        int arow = m0w + (lane & 15);
#pragma unroll
        for (int k4 = 0; k4 < 4; k4++) {
            uint32_t abyte = (uint32_t)((k4 * 32 + (lane >> 4) * 16) ^ ((arow & 7) << 4));
            ldsm4(qa[k4], sb + AQS + arow * 128 + abyte);
        }
    }

    float oc[8][4];
#pragma unroll
    for (int j = 0; j < 8; j++)
#pragma unroll
        for (int q = 0; q < 4; q++) oc[j][q] = 0.f;
    float ls0 = 0.f, ls1 = 0.f;

    int stage = 0;
    for (int kt = kt0; kt < kt1; kt++) {
        // prefetch next tile
        if (kt + 1 < kt1) {
            uint32_t kbuf = AK0 + (stage ^ 1) * 8192;
            uint32_t vbuf = AV0 + (stage ^ 1) * 8192;
            const __half* Kg = Kb + (size_t)(kt + 1) * 64 * HEAD;
            const __half* Vg = Vb + (size_t)(kt + 1) * 64 * HEAD;
#pragma unroll
            for (int it = 0; it < 4; it++) {
                int idx = tid + it * 128;
                int rr = idx >> 3, u = idx & 7;
                uint32_t dst = rr * 128 + ((u * 16) ^ ((rr & 7) << 4));
                cp16(sb + kbuf + dst, &Kg[rr * HEAD + u * 8]);
                cp16(sb + vbuf + dst, &Vg[rr * HEAD + u * 8]);
            }
            CP_COMMIT();
        }

        const uint32_t kbase = sb + AK0 + stage * 8192;
        const uint32_t vbase = sb + AV0 + stage * 8192;

        // ---- MMA1: S = Q @ K^T ----
        float sc[8][4];
#pragma unroll
        for (int j = 0; j < 8; j++)
#pragma unroll
            for (int q = 0; q < 4; q++) sc[j][q] = 0.f;
#pragma unroll
        for (int jj = 0; jj < 4; jj++) {
            int brow = jj * 16 + (lane & 7) + ((lane >> 4) << 3);
#pragma unroll
            for (int k4 = 0; k4 < 4; k4++) {
                uint32_t bby = (uint32_t)((k4 * 32 + ((lane >> 3) & 1) * 16) ^ ((brow & 7) << 4));
                uint32_t bk[4];
                ldsm4(bk, kbase + brow * 128 + bby);
                mma16816(sc[2 * jj],     qa[k4], bk[0], bk[1]);
                mma16816(sc[2 * jj + 1], qa[k4], bk[2], bk[3]);
            }
        }

        // ---- mask + exp2 + P store (warp-private rows) ----
        const bool diag = (kt == qt);
        const int lr0 = m0w + g, lr1 = lr0 + 8;
#pragma unroll
        for (int jn = 0; jn < 8; jn++) {
            int c0 = jn * 8 + 2 * tg;
            float p0, p1, p2, p3;
            if (diag) {
                p0 = (c0     <= lr0) ? ex2f(sc[jn][0]) : 0.f;
                p1 = (c0 + 1 <= lr0) ? ex2f(sc[jn][1]) : 0.f;
                p2 = (c0     <= lr1) ? ex2f(sc[jn][2]) : 0.f;
                p3 = (c0 + 1 <= lr1) ? ex2f(sc[jn][3]) : 0.f;
            } else {
                p0 = ex2f(sc[jn][0]); p1 = ex2f(sc[jn][1]);
                p2 = ex2f(sc[jn][2]); p3 = ex2f(sc[jn][3]);
            }
            ls0 += p0 + p1;
            ls1 += p2 + p3;
            *(uint32_t*)(smem + APS + lr0 * 128 + ((c0 * 2) ^ ((lr0 & 7) << 4))) =
                packh(__float2half_rn(p0), __float2half_rn(p1));
            *(uint32_t*)(smem + APS + lr1 * 128 + ((c0 * 2) ^ ((lr1 & 7) << 4))) =
                packh(__float2half_rn(p2), __float2half_rn(p3));
        }
        __syncwarp();

        // ---- MMA2: O += P @ V ----
        uint32_t pa[4][4];
        {
            int arow = m0w + (lane & 15);
#pragma unroll
            for (int k4 = 0; k4 < 4; k4++) {
                uint32_t abyte = (uint32_t)((k4 * 32 + (lane >> 4) * 16) ^ ((arow & 7) << 4));
                ldsm4(pa[k4], sb + APS + arow * 128 + abyte);
            }
        }
#pragma unroll
        for (int jj = 0; jj < 4; jj++) {
#pragma unroll
            for (int k4 = 0; k4 < 4; k4++) {
                int krow = k4 * 16 + (lane & 7) + (((lane >> 3) & 1) << 3);
                uint32_t vby = (uint32_t)(((jj * 16 + ((lane >> 4) << 3)) * 2) ^ ((krow & 7) << 4));
                uint32_t bv[4];
                ldsm4t(bv, vbase + krow * 128 + vby);
                mma16816(oc[2 * jj],     pa[k4], bv[0], bv[1]);
                mma16816(oc[2 * jj + 1], pa[k4], bv[2], bv[3]);
            }
        }

        if (kt + 1 < kt1) {
            CP_WAIT0();
            __syncthreads();
        }
        stage ^= 1;
    }

    // ---- reduce l within quads, write partials ----
    ls0 += __shfl_xor_sync(0xffffffffu, ls0, 1);
    ls0 += __shfl_xor_sync(0xffffffffu, ls0, 2);
    ls1 += __shfl_xor_sync(0xffffffffu, ls1, 1);
    ls1 += __shfl_xor_sync(0xffffffffu, ls1, 2);

    float* Op = gOp + (size_t)slot * 4096;
    const int lr0 = m0w + g, lr1 = lr0 + 8;
#pragma unroll
    for (int jn = 0; jn < 8; jn++) {
        int col = jn * 8 + 2 * tg;
        *(float2*)&Op[lr0 * 64 + col] = make_float2(oc[jn][0], oc[jn][1]);
        *(float2*)&Op[lr1 * 64 + col] = make_float2(oc[jn][2], oc[jn][3]);
    }
    if (tg == 0) {
        gLp[slot * 64 + lr0] = ls0;
        gLp[slot * 64 + lr1] = ls1;
    }
}

// ============================================================================
// Kernel 2b: combine partials + normalize. CTA = (b, qt); 256 threads;
// thread handles one 16-col strip of one row.
// ============================================================================
__global__ __launch_bounds__(256) void attn_comb(float* __restrict__ out)
{
    const int bid = blockIdx.x;
    const int qt  = bid & 63;
    const int b   = bid >> 6;
    const int tid = threadIdx.x;
    const int row = tid >> 2;
    const int cb  = (tid & 3) * 16;

    const int nch = (qt >> 4) + 1;
    int off0;
    if (qt < 16)      off0 = qt;
    else if (qt < 32) off0 = 16 + (qt - 16) * 2;
    else if (qt < 48) off0 = 48 + (qt - 32) * 3;
    else              off0 = 96 + (qt - 48) * 4;
    const int slot0 = b * 160 + off0;

    float acc[16];
#pragma unroll
    for (int i = 0; i < 16; i++) acc[i] = 0.f;
    float lsum = 0.f;

    for (int c = 0; c < nch; c++) {
        const float* Op = gOp + (size_t)(slot0 + c) * 4096 + row * 64 + cb;
        lsum += gLp[(slot0 + c) * 64 + row];
#pragma unroll
        for (int q = 0; q < 4; q++) {
            float4 v = *(const float4*)&Op[q * 4];
            acc[4 * q]     += v.x;
            acc[4 * q + 1] += v.y;
            acc[4 * q + 2] += v.z;
            acc[4 * q + 3] += v.w;
        }
    }

    const float inv = 1.0f / lsum;
    float* dst = out + ((size_t)(b * SEQ + qt * 64 + row)) * HEAD + cb;
#pragma unroll
    for (int q = 0; q < 4; q++) {
        float4 v = make_float4(acc[4 * q] * inv, acc[4 * q + 1] * inv,
                               acc[4 * q + 2] * inv, acc[4 * q + 3] * inv);
        *(float4*)&dst[q * 4] = v;
    }
}

// ============================================================================
// launch
// ============================================================================
extern "C" void kernel_launch(void* const* d_in, const int* in_sizes, int n_in,
                              void* d_out, int out_size)
{
    const float* x  = (const float*)d_in[0];
    const float* Wk = (const float*)d_in[1];
    const float* Wq = (const float*)d_in[2];
    const float* Wv = (const float*)d_in[3];
    float* out = (float*)d_out;

    cudaFuncSetAttribute(proj_mma, cudaFuncAttributeMaxDynamicSharedMemorySize, PSMEM);
    proj_mma<<<NTOK / 64, 256, PSMEM>>>(x, Wk, Wq, Wv);

    attn_part<<<NUNITS, 128>>>();
    attn_comb<<<256, 256>>>(out);
}

// round 7
// speedup vs baseline: 10.0957x; 1.1007x over previous
#include <cuda_runtime.h>
#include <cuda_fp16.h>
#include <cstdint>

#define BATCH 4
#define SEQ   4096
#define EMBED 512
#define HEAD  64
#define NTOK  (BATCH * SEQ)
// C^-0.5 * log2(e): Q pre-scale so softmax uses raw ex2
#define QSC2  (0.04419417382415922f * 1.4426950408889634f)

#define NUNITS 640          // split-K work units (160 per batch)

// ---------------- scratch (device globals) ----------------
__device__ __half gK16[NTOK * HEAD];   // [t][h]
__device__ __half gQ16[NTOK * HEAD];   // [t][h], pre-scaled by QSC2
__device__ __half gV16[NTOK * HEAD];   // [t][h]
__device__ __half gW16[192 * EMBED];   // [Wk;Wq;Wv] rows, fp16
__device__ float  gOp[NUNITS * 64 * 64];  // partial O (unnormalized)
__device__ float  gLp[NUNITS * 64];       // partial l

// ---------------- helpers ----------------
__device__ __forceinline__ uint32_t smem_u32(const void* p) {
    uint32_t a;
    asm("{ .reg .u64 t; cvta.to.shared.u64 t, %1; cvt.u32.u64 %0, t; }" : "=r"(a) : "l"(p));
    return a;
}
__device__ __forceinline__ void ldsm4(uint32_t* r, uint32_t addr) {
    asm volatile("ldmatrix.sync.aligned.m8n8.x4.shared.b16 {%0,%1,%2,%3}, [%4];"
                 : "=r"(r[0]), "=r"(r[1]), "=r"(r[2]), "=r"(r[3]) : "r"(addr));
}
__device__ __forceinline__ void ldsm4t(uint32_t* r, uint32_t addr) {
    asm volatile("ldmatrix.sync.aligned.m8n8.x4.trans.shared.b16 {%0,%1,%2,%3}, [%4];"
                 : "=r"(r[0]), "=r"(r[1]), "=r"(r[2]), "=r"(r[3]) : "r"(addr));
}
__device__ __forceinline__ void mma16816(float* c, const uint32_t* a, uint32_t b0, uint32_t b1) {
    asm volatile(
        "mma.sync.aligned.m16n8k16.row.col.f32.f16.f16.f32 "
        "{%0,%1,%2,%3}, {%4,%5,%6,%7}, {%8,%9}, {%0,%1,%2,%3};"
        : "+f"(c[0]), "+f"(c[1]), "+f"(c[2]), "+f"(c[3])
        : "r"(a[0]), "r"(a[1]), "r"(a[2]), "r"(a[3]), "r"(b0), "r"(b1));
}
__device__ __forceinline__ uint32_t packh(__half a, __half b) {
    __half2 t = __halves2half2(a, b);
    return *(uint32_t*)&t;
}
__device__ __forceinline__ float ex2f(float x) {
    float y;
    asm("ex2.approx.f32 %0, %1;" : "=f"(y) : "f"(x));
    return y;
}
__device__ __forceinline__ void cp16(uint32_t dst, const void* src) {
    asm volatile("cp.async.cg.shared.global [%0], [%1], 16;"
                 :: "r"(dst), "l"(__cvta_generic_to_global(src)) : "memory");
}
#define CP_COMMIT() asm volatile("cp.async.commit_group;" ::: "memory")
#define CP_WAIT0()  asm volatile("cp.async.wait_group 0;" ::: "memory")

// ============================================================================
// Kernel 0: weights fp32 -> fp16, stacked [Wk;Wq;Wv] = [192][512], 4/thread
// ============================================================================
__global__ __launch_bounds__(128) void w16_kernel(
    const float* __restrict__ Wk, const float* __restrict__ Wq,
    const float* __restrict__ Wv)
{
    int i4 = (blockIdx.x * 128 + threadIdx.x) * 4;   // 0..98300
    const float* src;
    int off;
    if (i4 < 64 * EMBED)       { src = Wk; off = i4; }
    else if (i4 < 128 * EMBED) { src = Wq; off = i4 - 64 * EMBED; }
    else                       { src = Wv; off = i4 - 128 * EMBED; }
    float4 f = *(const float4*)&src[off];
    *(uint2*)&gW16[i4] = make_uint2(packh(__float2half_rn(f.x), __float2half_rn(f.y)),
                                    packh(__float2half_rn(f.z), __float2half_rn(f.w)));
}

// ============================================================================
// Kernel 1: KQV projection via fp16 mma.sync.
// CTA: 64 rows x 192 cols, 256 threads = 8 warps: warp (h=wid>>2) covers
// rows (wid&3)*16, cols h*96. W staged via cp.async (fp16, pre-converted);
// x converted inline. Double-buffered; one __syncthreads per 64-K chunk.
// ============================================================================
#define PX(s) ((s) * 8192)             // 2 x 8KB x buffers
#define PW(s) (16384 + (s) * 24576)    // 2 x 24KB W buffers
#define PSMEM 65536

__global__ __launch_bounds__(256) void proj_mma(const float* __restrict__ x)
{
    extern __shared__ __align__(16) uint8_t smem[];
    const uint32_t sb = smem_u32(smem);

    const int tid  = threadIdx.x;
    const int wid  = tid >> 5;
    const int lane = tid & 31;
    const int wm   = (wid & 3) * 16;    // warp row base
    const int h    = wid >> 2;          // warp n-half (0: cols 0-95, 1: 96-191)
    const int g    = lane >> 2;
    const int tg   = lane & 3;
    const int mblk = blockIdx.x * 64;

    float c[12][4];
#pragma unroll
    for (int j = 0; j < 12; j++)
#pragma unroll
        for (int q = 0; q < 4; q++) c[j][q] = 0.f;

    // W chunk stage: 192 rows x 64 k fp16 via cp.async (6 cp / thread)
#define STAGE_W(kc, s)                                                              \
    do {                                                                            \
        _Pragma("unroll")                                                           \
        for (int it = 0; it < 6; it++) {                                            \
            int idx = tid + it * 256;          /* 0..1535 uint4s */                 \
            int r = idx >> 3, u = idx & 7;                                          \
            uint32_t dst = r * 128 + ((u * 16) ^ ((r & 7) << 4));                   \
            cp16(sb + PW(s) + dst, &gW16[(size_t)r * EMBED + (kc) * 64 + u * 8]);   \
        }                                                                           \
    } while (0)

    // x chunk stage: 64 rows x 64 k fp32 -> fp16 inline (4 LDG.128 / thread)
#define STAGE_X(kc, s)                                                              \
    do {                                                                            \
        _Pragma("unroll")                                                           \
        for (int it = 0; it < 4; it++) {                                            \
            int idx = tid + it * 256;          /* 0..1023 float4s */                \
            int r = idx >> 4, c4 = idx & 15;                                        \
            float4 f = *(const float4*)&x[(size_t)(mblk + r) * EMBED + (kc) * 64 + c4 * 4]; \
            uint32_t dst = r * 128 + ((c4 * 8) ^ ((r & 7) << 4));                   \
            *(uint2*)(smem + PX(s) + dst) =                                         \
                make_uint2(packh(__float2half_rn(f.x), __float2half_rn(f.y)),       \
                           packh(__float2half_rn(f.z), __float2half_rn(f.w)));      \
        }                                                                           \
    } while (0)

    STAGE_W(0, 0);
    CP_COMMIT();
    STAGE_X(0, 0);
    CP_WAIT0();
    __syncthreads();

    for (int kc = 0; kc < 8; kc++) {
        const int s = kc & 1;
        if (kc < 7) {
            STAGE_W(kc + 1, s ^ 1);
            CP_COMMIT();
            STAGE_X(kc + 1, s ^ 1);
        }

#pragma unroll
        for (int ks = 0; ks < 4; ks++) {
            uint32_t ah[4];
            int arow = wm + (lane & 15);
            uint32_t abyte = (uint32_t)((ks * 32 + (lane >> 4) * 16) ^ ((arow & 7) << 4));
            ldsm4(ah, sb + PX(s) + arow * 128 + abyte);
#pragma unroll
            for (int jj = 0; jj < 6; jj++) {
                uint32_t b[4];
                int brow = h * 96 + jj * 16 + (lane & 7) + ((lane >> 4) << 3);
                uint32_t bby = (uint32_t)((ks * 32 + ((lane >> 3) & 1) * 16) ^ ((brow & 7) << 4));
                ldsm4(b, sb + PW(s) + brow * 128 + bby);
                mma16816(c[2 * jj],     ah, b[0], b[1]);
                mma16816(c[2 * jj + 1], ah, b[2], b[3]);
            }
        }
        if (kc < 7) CP_WAIT0();
        __syncthreads();
    }
#undef STAGE_W
#undef STAGE_X

    // epilogue: global col = h*96 + j*8 + 2tg; 0-63 K, 64-127 Q (scaled), 128-191 V
    const int m0 = mblk + wm + g;
#pragma unroll
    for (int j = 0; j < 12; j++) {
        int col = h * 96 + j * 8 + 2 * tg;
        if (col < 64) {
            *(uint32_t*)&gK16[(size_t)m0 * HEAD + col] =
                packh(__float2half_rn(c[j][0]), __float2half_rn(c[j][1]));
            *(uint32_t*)&gK16[(size_t)(m0 + 8) * HEAD + col] =
                packh(__float2half_rn(c[j][2]), __float2half_rn(c[j][3]));
        } else if (col < 128) {
            int hh = col - 64;
            *(uint32_t*)&gQ16[(size_t)m0 * HEAD + hh] =
                packh(__float2half_rn(c[j][0] * QSC2), __float2half_rn(c[j][1] * QSC2));
            *(uint32_t*)&gQ16[(size_t)(m0 + 8) * HEAD + hh] =
                packh(__float2half_rn(c[j][2] * QSC2), __float2half_rn(c[j][3] * QSC2));
        } else {
            int hh = col - 128;
            *(uint32_t*)&gV16[(size_t)m0 * HEAD + hh] =
                packh(__float2half_rn(c[j][0]), __float2half_rn(c[j][1]));
            *(uint32_t*)&gV16[(size_t)(m0 + 8) * HEAD + hh] =
                packh(__float2half_rn(c[j][2]), __float2half_rn(c[j][3]));
        }
    }
}

// ============================================================================
// Kernel 2a: attention pass 1 (split-K). Unit = (b, 64-q-tile, <=16 key tiles).
// 128 threads, 4 warps; cp.async double-buffered K/V. Writes unnormalized
// partial O (fp32 64x64) + partial l (64) to gmem.
// ============================================================================
#define AQS  0            // 8KB Q
#define AK0  8192         // 2x8KB K
#define AV0  24576        // 2x8KB V
#define APS  40960        // 8KB P

__global__ __launch_bounds__(128, 4) void attn_part(void)
{
    __shared__ __align__(16) uint8_t smem[49152];
    const uint32_t sb = smem_u32(smem);

    // big-qt units first
    const int slot = (NUNITS - 1) - blockIdx.x;
    const int b = slot / 160;
    const int r = slot % 160;
    int qt, ch;
    if (r < 16)      { qt = r;                 ch = 0; }
    else if (r < 48) { qt = 16 + ((r - 16) >> 1); ch = (r - 16) & 1; }
    else if (r < 96) { qt = 32 + (r - 48) / 3;    ch = (r - 48) % 3; }
    else             { qt = 48 + ((r - 96) >> 2); ch = (r - 96) & 3; }
    const int kt0 = ch * 16;
    const int kt1 = (kt0 + 16 < qt + 1) ? (kt0 + 16) : (qt + 1);

    const int tid  = threadIdx.x;
    const int wid  = tid >> 5;
    const int lane = tid & 31;
    const int m0w  = wid * 16;
    const int g    = lane >> 2;
    const int tg   = lane & 3;

    const __half* __restrict__ Qg = gQ16 + (size_t)(b * SEQ + qt * 64) * HEAD;
    const __half* __restrict__ Kb = gK16 + (size_t)(b * SEQ) * HEAD;
    const __half* __restrict__ Vb = gV16 + (size_t)(b * SEQ) * HEAD;

    // stage Q + first K/V tile
#pragma unroll
    for (int it = 0; it < 4; it++) {
        int idx = tid + it * 128;          // 0..511
        int rr = idx >> 3, u = idx & 7;
        uint32_t dst = rr * 128 + ((u * 16) ^ ((rr & 7) << 4));
        cp16(sb + AQS + dst, &Qg[rr * HEAD + u * 8]);
        cp16(sb + AK0 + dst, &Kb[(size_t)(kt0 * 64 + rr) * HEAD + u * 8]);
        cp16(sb + AV0 + dst, &Vb[(size_t)(kt0 * 64 + rr) * HEAD + u * 8]);
    }
    CP_COMMIT();
    CP_WAIT0();
    __syncthreads();

    uint32_t qa[4][4];
    {
        int arow = m0w + (lane & 15);
#pragma unroll
        for (int k4 = 0; k4 < 4; k4++) {
            uint32_t abyte = (uint32_t)((k4 * 32 + (lane >> 4) * 16) ^ ((arow & 7) << 4));
            ldsm4(qa[k4], sb + AQS + arow * 128 + abyte);
        }
    }

    float oc[8][4];
#pragma unroll
    for (int j = 0; j < 8; j++)
#pragma unroll
        for (int q = 0; q < 4; q++) oc[j][q] = 0.f;
    float ls0 = 0.f, ls1 = 0.f;

    int stage = 0;
    for (int kt = kt0; kt < kt1; kt++) {
        // prefetch next tile
        if (kt + 1 < kt1) {
            uint32_t kbuf = AK0 + (stage ^ 1) * 8192;
            uint32_t vbuf = AV0 + (stage ^ 1) * 8192;
            const __half* Kg = Kb + (size_t)(kt + 1) * 64 * HEAD;
            const __half* Vg = Vb + (size_t)(kt + 1) * 64 * HEAD;
#pragma unroll
            for (int it = 0; it < 4; it++) {
                int idx = tid + it * 128;
                int rr = idx >> 3, u = idx & 7;
                uint32_t dst = rr * 128 + ((u * 16) ^ ((rr & 7) << 4));
                cp16(sb + kbuf + dst, &Kg[rr * HEAD + u * 8]);
                cp16(sb + vbuf + dst, &Vg[rr * HEAD + u * 8]);
            }
            CP_COMMIT();
        }

        const uint32_t kbase = sb + AK0 + stage * 8192;
        const uint32_t vbase = sb + AV0 + stage * 8192;

        // ---- MMA1: S = Q @ K^T ----
        float sc[8][4];
#pragma unroll
        for (int j = 0; j < 8; j++)
#pragma unroll
            for (int q = 0; q < 4; q++) sc[j][q] = 0.f;
#pragma unroll
        for (int jj = 0; jj < 4; jj++) {
            int brow = jj * 16 + (lane & 7) + ((lane >> 4) << 3);
#pragma unroll
            for (int k4 = 0; k4 < 4; k4++) {
                uint32_t bby = (uint32_t)((k4 * 32 + ((lane >> 3) & 1) * 16) ^ ((brow & 7) << 4));
                uint32_t bk[4];
                ldsm4(bk, kbase + brow * 128 + bby);
                mma16816(sc[2 * jj],     qa[k4], bk[0], bk[1]);
                mma16816(sc[2 * jj + 1], qa[k4], bk[2], bk[3]);
            }
        }

        // ---- mask + exp2 + P store (warp-private rows) ----
        const bool diag = (kt == qt);
        const int lr0 = m0w + g, lr1 = lr0 + 8;
#pragma unroll
        for (int jn = 0; jn < 8; jn++) {
            int c0 = jn * 8 + 2 * tg;
            float p0, p1, p2, p3;
            if (diag) {
                p0 = (c0     <= lr0) ? ex2f(sc[jn][0]) : 0.f;
                p1 = (c0 + 1 <= lr0) ? ex2f(sc[jn][1]) : 0.f;
                p2 = (c0     <= lr1) ? ex2f(sc[jn][2]) : 0.f;
                p3 = (c0 + 1 <= lr1) ? ex2f(sc[jn][3]) : 0.f;
            } else {
                p0 = ex2f(sc[jn][0]); p1 = ex2f(sc[jn][1]);
                p2 = ex2f(sc[jn][2]); p3 = ex2f(sc[jn][3]);
            }
            ls0 += p0 + p1;
            ls1 += p2 + p3;
            *(uint32_t*)(smem + APS + lr0 * 128 + ((c0 * 2) ^ ((lr0 & 7) << 4))) =
                packh(__float2half_rn(p0), __float2half_rn(p1));
            *(uint32_t*)(smem + APS + lr1 * 128 + ((c0 * 2) ^ ((lr1 & 7) << 4))) =
                packh(__float2half_rn(p2), __float2half_rn(p3));
        }
        __syncwarp();

        // ---- MMA2: O += P @ V ----
        uint32_t pa[4][4];
        {
            int arow = m0w + (lane & 15);
#pragma unroll
            for (int k4 = 0; k4 < 4; k4++) {
                uint32_t abyte = (uint32_t)((k4 * 32 + (lane >> 4) * 16) ^ ((arow & 7) << 4));
                ldsm4(pa[k4], sb + APS + arow * 128 + abyte);
            }
        }
#pragma unroll
        for (int jj = 0; jj < 4; jj++) {
#pragma unroll
            for (int k4 = 0; k4 < 4; k4++) {
                int krow = k4 * 16 + (lane & 7) + (((lane >> 3) & 1) << 3);
                uint32_t vby = (uint32_t)(((jj * 16 + ((lane >> 4) << 3)) * 2) ^ ((krow & 7) << 4));
                uint32_t bv[4];
                ldsm4t(bv, vbase + krow * 128 + vby);
                mma16816(oc[2 * jj],     pa[k4], bv[0], bv[1]);
                mma16816(oc[2 * jj + 1], pa[k4], bv[2], bv[3]);
            }
        }

        if (kt + 1 < kt1) {
            CP_WAIT0();
            __syncthreads();
        }
        stage ^= 1;
    }

    // ---- reduce l within quads, write partials ----
    ls0 += __shfl_xor_sync(0xffffffffu, ls0, 1);
    ls0 += __shfl_xor_sync(0xffffffffu, ls0, 2);
    ls1 += __shfl_xor_sync(0xffffffffu, ls1, 1);
    ls1 += __shfl_xor_sync(0xffffffffu, ls1, 2);

    float* Op = gOp + (size_t)slot * 4096;
    const int lr0 = m0w + g, lr1 = lr0 + 8;
#pragma unroll
    for (int jn = 0; jn < 8; jn++) {
        int col = jn * 8 + 2 * tg;
        *(float2*)&Op[lr0 * 64 + col] = make_float2(oc[jn][0], oc[jn][1]);
        *(float2*)&Op[lr1 * 64 + col] = make_float2(oc[jn][2], oc[jn][3]);
    }
    if (tg == 0) {
        gLp[slot * 64 + lr0] = ls0;
        gLp[slot * 64 + lr1] = ls1;
    }
}

// ============================================================================
// Kernel 2b: combine partials + normalize. CTA = (b, qt); 256 threads;
// thread handles one 16-col strip of one row.
// ============================================================================
__global__ __launch_bounds__(256) void attn_comb(float* __restrict__ out)
{
    const int bid = blockIdx.x;
    const int qt  = bid & 63;
    const int b   = bid >> 6;
    const int tid = threadIdx.x;
    const int row = tid >> 2;
    const int cb  = (tid & 3) * 16;

    const int nch = (qt >> 4) + 1;
    int off0;
    if (qt < 16)      off0 = qt;
    else if (qt < 32) off0 = 16 + (qt - 16) * 2;
    else if (qt < 48) off0 = 48 + (qt - 32) * 3;
    else              off0 = 96 + (qt - 48) * 4;
    const int slot0 = b * 160 + off0;

    float acc[16];
#pragma unroll
    for (int i = 0; i < 16; i++) acc[i] = 0.f;
    float lsum = 0.f;

    for (int c = 0; c < nch; c++) {
        const float* Op = gOp + (size_t)(slot0 + c) * 4096 + row * 64 + cb;
        lsum += gLp[(slot0 + c) * 64 + row];
#pragma unroll
        for (int q = 0; q < 4; q++) {
            float4 v = *(const float4*)&Op[q * 4];
            acc[4 * q]     += v.x;
            acc[4 * q + 1] += v.y;
            acc[4 * q + 2] += v.z;
            acc[4 * q + 3] += v.w;
        }
    }

    const float inv = 1.0f / lsum;
    float* dst = out + ((size_t)(b * SEQ + qt * 64 + row)) * HEAD + cb;
#pragma unroll
    for (int q = 0; q < 4; q++) {
        float4 v = make_float4(acc[4 * q] * inv, acc[4 * q + 1] * inv,
                               acc[4 * q + 2] * inv, acc[4 * q + 3] * inv);
        *(float4*)&dst[q * 4] = v;
    }
}

// ============================================================================
// launch
// ============================================================================
extern "C" void kernel_launch(void* const* d_in, const int* in_sizes, int n_in,
                              void* d_out, int out_size)
{
    const float* x  = (const float*)d_in[0];
    const float* Wk = (const float*)d_in[1];
    const float* Wq = (const float*)d_in[2];
    const float* Wv = (const float*)d_in[3];
    float* out = (float*)d_out;

    w16_kernel<<<192, 128>>>(Wk, Wq, Wv);

    cudaFuncSetAttribute(proj_mma, cudaFuncAttributeMaxDynamicSharedMemorySize, PSMEM);
    proj_mma<<<NTOK / 64, 256, PSMEM>>>(x);

    attn_part<<<NUNITS, 128>>>();
    attn_comb<<<256, 256>>>(out);
}